// round 3
// baseline (speedup 1.0000x reference)
#include <cuda_runtime.h>
#include <math.h>
#include <stdint.h>

#define DIM 768
#define NHEAD 12
#define HD 64
#define BATCH 8
#define SEQ 1024
#define TOKENS (BATCH*SEQ)   // 8192
#define QKV_N (3*DIM)        // 2304

// Scratch (no allocation allowed)
__device__ float g_qkv[TOKENS * QKV_N];        // plain fp32 qkv (q,k get permuted in-place/elsewhere)
__device__ float g_attn[TOKENS * DIM];         // attention out, k-permuted tf32
__device__ float g_xP [TOKENS * DIM];          // x, k-permuted tf32
__device__ float g_wqP[QKV_N * DIM];           // qkv_w, k-permuted tf32
__device__ float g_wpP[DIM * DIM];             // proj_w, k-permuted tf32
__device__ float g_kP [BATCH * NHEAD * SEQ * HD];  // normed K, d-permuted tf32, [bh][j][64]
__device__ float g_vP [BATCH * NHEAD * HD * SEQ];  // V^T, j-permuted tf32,   [bh][d][1024]

__device__ __forceinline__ float cvt_tf32(float x) {
    float r; asm("cvt.rna.tf32.f32 %0, %1;\n" : "=f"(r) : "f"(x)); return r;
}
__device__ __forceinline__ float ex2f(float x) {
    float r; asm("ex2.approx.f32 %0, %1;\n" : "=f"(r) : "f"(x)); return r;
}
__device__ __forceinline__ void mma_tf32(float c[4],
    uint32_t a0, uint32_t a1, uint32_t a2, uint32_t a3, uint32_t b0, uint32_t b1)
{
    asm volatile(
        "mma.sync.aligned.m16n8k8.row.col.f32.tf32.tf32.f32 "
        "{%0,%1,%2,%3}, {%4,%5,%6,%7}, {%8,%9}, {%0,%1,%2,%3};\n"
        : "+f"(c[0]), "+f"(c[1]), "+f"(c[2]), "+f"(c[3])
        : "r"(a0), "r"(a1), "r"(a2), "r"(a3), "r"(b0), "r"(b1));
}

// ---------------------------------------------------------------------------
// Permute+cvt: per-row, per-32-chunk permutation pk(k) = (k&3)*8 + (k>>2),
// with cvt.rna.tf32. out[r][c32 + p] = cvt(in[r][c32 + kinv(p)]).
// Thread handles one output float4 (gathers 4 scalars).
// ---------------------------------------------------------------------------
__global__ __launch_bounds__(256) void permute32_cvt(
    const float* __restrict__ in, float* __restrict__ out, int K)
{
    int idx = blockIdx.x * 256 + threadIdx.x;       // float4 index
    int q = idx % (K / 4);
    int r = idx / (K / 4);
    int c32 = (q >> 3) * 32;
    int u = q & 7;
    const float* src = in + (size_t)r * K + c32;
    float4 v;
    int base = 16 * (u & 1) + (u >> 1);             // k_e = base + 4e
    v.x = cvt_tf32(src[base +  0]);
    v.y = cvt_tf32(src[base +  4]);
    v.z = cvt_tf32(src[base +  8]);
    v.w = cvt_tf32(src[base + 12]);
    *(float4*)(out + (size_t)r * K + c32 + u * 4) = v;
}

// ---------------------------------------------------------------------------
// TF32 GEMM on pre-permuted operands. C[m][n] = sum_k A[m][k]*W[n][k] + bias.
// BM=BN=128, BK=32, 256 threads (8 warps 2x4), warp tile 64x32, LDT=36.
// smem tiles are straight float4 copies (layout identical to gmem).
// ---------------------------------------------------------------------------
#define LDT 36
__global__ __launch_bounds__(256) void sgemm_tf32p(
    const float* __restrict__ A, const float* __restrict__ W,
    const float* __restrict__ bias, float* __restrict__ C,
    int M, int N, int K)
{
    __shared__ float As[128 * LDT];
    __shared__ float Ws[128 * LDT];

    const int bm = blockIdx.y * 128, bn = blockIdx.x * 128;
    const int t = threadIdx.x, lane = t & 31, warp = t >> 5;
    const int wm = (warp & 1) * 64, wn = (warp >> 1) * 32;
    const int g = lane >> 2, tg = lane & 3;

    float acc[4][4][4];
#pragma unroll
    for (int i = 0; i < 4; i++)
#pragma unroll
        for (int j = 0; j < 4; j++)
#pragma unroll
            for (int c = 0; c < 4; c++) acc[i][j][c] = 0.f;

    for (int k0 = 0; k0 < K; k0 += 32) {
#pragma unroll
        for (int l = 0; l < 4; l++) {
            int s = t + l * 256;
            int r = s >> 3, c = (s & 7) * 4;
            *(float4*)(As + r * LDT + c) =
                *(const float4*)(A + (size_t)(bm + r) * K + k0 + c);
            *(float4*)(Ws + r * LDT + c) =
                *(const float4*)(W + (size_t)(bn + r) * K + k0 + c);
        }
        __syncthreads();

#pragma unroll
        for (int h = 0; h < 2; h++) {
            float4 fa[4][2], fw[4];
#pragma unroll
            for (int im = 0; im < 4; im++) {
                const float* p = As + (wm + im * 16 + g) * LDT + tg * 8 + 4 * h;
                fa[im][0] = *(const float4*)p;
                fa[im][1] = *(const float4*)(p + 8 * LDT);
            }
#pragma unroll
            for (int jn = 0; jn < 4; jn++) {
                const float* p = Ws + (wn + jn * 8 + g) * LDT + tg * 8 + 4 * h;
                fw[jn] = *(const float4*)p;
            }
#pragma unroll
            for (int s1 = 0; s1 < 2; s1++) {
#pragma unroll
                for (int im = 0; im < 4; im++) {
                    uint32_t a0 = __float_as_uint((&fa[im][0].x)[2 * s1]);
                    uint32_t a2 = __float_as_uint((&fa[im][0].x)[2 * s1 + 1]);
                    uint32_t a1 = __float_as_uint((&fa[im][1].x)[2 * s1]);
                    uint32_t a3 = __float_as_uint((&fa[im][1].x)[2 * s1 + 1]);
#pragma unroll
                    for (int jn = 0; jn < 4; jn++) {
                        uint32_t b0 = __float_as_uint((&fw[jn].x)[2 * s1]);
                        uint32_t b1 = __float_as_uint((&fw[jn].x)[2 * s1 + 1]);
                        mma_tf32(acc[im][jn], a0, a1, a2, a3, b0, b1);
                    }
                }
            }
        }
        __syncthreads();
    }

#pragma unroll
    for (int im = 0; im < 4; im++) {
        int r0 = bm + wm + im * 16 + g;
#pragma unroll
        for (int jn = 0; jn < 4; jn++) {
            int c0 = bn + wn + jn * 8 + 2 * tg;
            float bx = bias[c0], by = bias[c0 + 1];
            float2 v0 = make_float2(acc[im][jn][0] + bx, acc[im][jn][1] + by);
            float2 v1 = make_float2(acc[im][jn][2] + bx, acc[im][jn][3] + by);
            *(float2*)(C + (size_t)r0 * N + c0) = v0;
            *(float2*)(C + (size_t)(r0 + 8) * N + c0) = v1;
        }
    }
}

// ---------------------------------------------------------------------------
// LayerNorm q,k head segments. q: in-place, d-permuted + cvt.
// k: -> g_kP[bh][j][pd], cvt. pd(d) = (d&7)*8 + (d>>3).
// ---------------------------------------------------------------------------
__global__ __launch_bounds__(256) void qk_layernorm_p(
    float* __restrict__ qkv, float* __restrict__ kP,
    const float* __restrict__ gamma, const float* __restrict__ beta)
{
    int gwarp = (blockIdx.x * blockDim.x + threadIdx.x) >> 5;
    int lane  = threadIdx.x & 31;
    int h = gwarp % NHEAD;
    int tmp = gwarp / NHEAD;
    int p = tmp & 1;
    int m = tmp >> 1;
    if (m >= TOKENS) return;

    float* row = qkv + (size_t)m * QKV_N + p * DIM + h * HD;
    float2 v = *(float2*)(row + lane * 2);

    float s = v.x + v.y;
#pragma unroll
    for (int o = 16; o; o >>= 1) s += __shfl_xor_sync(0xffffffffu, s, o);
    float mu = s * (1.f / 64.f);
    float dx = v.x - mu, dy = v.y - mu;
    float vs = dx * dx + dy * dy;
#pragma unroll
    for (int o = 16; o; o >>= 1) vs += __shfl_xor_sync(0xffffffffu, vs, o);
    float rstd = rsqrtf(vs * (1.f / 64.f) + 1e-5f);

    float r0 = cvt_tf32(dx * rstd * gamma[lane * 2 + 0] + beta[lane * 2 + 0]);
    float r1 = cvt_tf32(dy * rstd * gamma[lane * 2 + 1] + beta[lane * 2 + 1]);

    int pd0 = (lane & 3) * 16 + (lane >> 2);   // pd(2*lane); pd(2*lane+1)=pd0+8
    if (p == 0) {
        __syncwarp();                          // all reads done before scatter
        row[pd0] = r0;
        row[pd0 + 8] = r1;
    } else {
        int b = m >> 10, n = m & 1023;
        float* krow = kP + ((size_t)(b * NHEAD + h) * SEQ + n) * HD;
        krow[pd0] = r0;
        krow[pd0 + 8] = r1;
    }
}

// ---------------------------------------------------------------------------
// V transpose: g_qkv v-part -> g_vP[bh][d][64-chunk j-permuted], cvt.
// Thread = (bh, u, d): gathers 4 rows, writes one float4.
// ---------------------------------------------------------------------------
__global__ __launch_bounds__(256) void v_transpose_p(
    const float* __restrict__ qkv, float* __restrict__ vP)
{
    int bx = blockIdx.x;                 // 96 bh * 16 jt * 4 ug = 6144
    int t = threadIdx.x;
    int d  = t & 63;
    int u  = (bx & 3) * 4 + (t >> 6);    // 0..15
    int jt = (bx >> 2) & 15;
    int bh = bx >> 6;
    int b = bh / NHEAD, h = bh % NHEAD;

    int jb = 32 * (u & 1) + (u >> 1);    // j_e = jt*64 + jb + 8e
    const float* src = qkv + ((size_t)(b * SEQ + jt * 64 + jb)) * QKV_N
                       + 2 * DIM + h * HD + d;
    float4 v;
    v.x = cvt_tf32(src[0]);
    v.y = cvt_tf32(src[ 8 * QKV_N]);
    v.z = cvt_tf32(src[16 * QKV_N]);
    v.w = cvt_tf32(src[24 * QKV_N]);
    *(float4*)(vP + ((size_t)bh * HD + d) * SEQ + jt * 64 + u * 4) = v;
}

// ---------------------------------------------------------------------------
// Flash attention, TF32 mma, permuted operands. 128 threads = 4 warps,
// q-tile 64 (warp w: rows 16w..16w+15). All frag loads are lds.128.
// Output written k-permuted + cvt for the proj GEMM.
// ---------------------------------------------------------------------------
#define LQ 68
__global__ __launch_bounds__(128) void attn_tf32p(
    const float* __restrict__ qkv, const float* __restrict__ kP,
    const float* __restrict__ vP, float* __restrict__ out)
{
    __shared__ float Ks[64 * LQ];
    __shared__ float Vs[64 * LQ];

    const int q0 = blockIdx.x * 64;
    const int bh = blockIdx.y;
    const int b = bh / NHEAD, h = bh % NHEAD;
    const int t = threadIdx.x, lane = t & 31, warp = t >> 5;
    const int g = lane >> 2, tg = lane & 3;
    const size_t kvbase = (size_t)bh * SEQ * HD;   // for kP ([j][64]) and vP ([d][1024])
    const float sc = 0.125f * 1.4426950408889634f;

    // Stage Q (already permuted+normed tf32) via Ks
#pragma unroll
    for (int l = 0; l < 8; l++) {
        int s = t + l * 128, r = s >> 4, c = (s & 15) * 4;
        *(float4*)(Ks + r * LQ + c) =
            *(const float4*)(qkv + ((size_t)(b * SEQ + q0 + r)) * QKV_N + h * HD + c);
    }
    __syncthreads();

    uint32_t Qa[8][4];
    {
        const float* rA = Ks + (warp * 16 + g) * LQ;
        const float* rB = rA + 8 * LQ;
        float4 fA0 = *(const float4*)(rA + tg * 8);
        float4 fA1 = *(const float4*)(rA + tg * 8 + 4);
        float4 fA2 = *(const float4*)(rA + (tg + 4) * 8);
        float4 fA3 = *(const float4*)(rA + (tg + 4) * 8 + 4);
        float4 fB0 = *(const float4*)(rB + tg * 8);
        float4 fB1 = *(const float4*)(rB + tg * 8 + 4);
        float4 fB2 = *(const float4*)(rB + (tg + 4) * 8);
        float4 fB3 = *(const float4*)(rB + (tg + 4) * 8 + 4);
#pragma unroll
        for (int kd = 0; kd < 8; kd++) {
            Qa[kd][0] = __float_as_uint(kd < 4 ? (&fA0.x)[kd] : (&fA1.x)[kd - 4]);
            Qa[kd][1] = __float_as_uint(kd < 4 ? (&fB0.x)[kd] : (&fB1.x)[kd - 4]);
            Qa[kd][2] = __float_as_uint(kd < 4 ? (&fA2.x)[kd] : (&fA3.x)[kd - 4]);
            Qa[kd][3] = __float_as_uint(kd < 4 ? (&fB2.x)[kd] : (&fB3.x)[kd - 4]);
        }
    }
    __syncthreads();

    float Oacc[8][4];
#pragma unroll
    for (int dn = 0; dn < 8; dn++)
#pragma unroll
        for (int c = 0; c < 4; c++) Oacc[dn][c] = 0.f;
    float m0 = -1e30f, m1 = -1e30f, l0 = 0.f, l1 = 0.f;

    for (int kv = 0; kv < SEQ; kv += 64) {
        // K tile: rows j (permuted d). V tile: rows d (permuted j within chunk).
#pragma unroll
        for (int l = 0; l < 8; l++) {
            int s = t + l * 128, r = s >> 4, c = (s & 15) * 4;
            *(float4*)(Ks + r * LQ + c) =
                *(const float4*)(kP + kvbase + (size_t)(kv + r) * HD + c);
            *(float4*)(Vs + r * LQ + c) =
                *(const float4*)(vP + kvbase + (size_t)r * SEQ + kv + c);
        }
        __syncthreads();

        // S = Q @ K^T
        float S[8][4];
#pragma unroll
        for (int jn = 0; jn < 8; jn++)
#pragma unroll
            for (int c = 0; c < 4; c++) S[jn][c] = 0.f;
#pragma unroll
        for (int jp = 0; jp < 4; jp++) {
            const float* rb0 = Ks + (jp * 16 + g) * LQ;
            const float* rb1 = rb0 + 8 * LQ;
            float4 A0 = *(const float4*)(rb0 + tg * 8);
            float4 A1 = *(const float4*)(rb0 + tg * 8 + 4);
            float4 A2 = *(const float4*)(rb0 + (tg + 4) * 8);
            float4 A3 = *(const float4*)(rb0 + (tg + 4) * 8 + 4);
            float4 B0 = *(const float4*)(rb1 + tg * 8);
            float4 B1 = *(const float4*)(rb1 + tg * 8 + 4);
            float4 B2 = *(const float4*)(rb1 + (tg + 4) * 8);
            float4 B3 = *(const float4*)(rb1 + (tg + 4) * 8 + 4);
#pragma unroll
            for (int kd = 0; kd < 8; kd++) {
                uint32_t b0a = __float_as_uint(kd < 4 ? (&A0.x)[kd] : (&A1.x)[kd - 4]);
                uint32_t b1a = __float_as_uint(kd < 4 ? (&A2.x)[kd] : (&A3.x)[kd - 4]);
                uint32_t b0b = __float_as_uint(kd < 4 ? (&B0.x)[kd] : (&B1.x)[kd - 4]);
                uint32_t b1b = __float_as_uint(kd < 4 ? (&B2.x)[kd] : (&B3.x)[kd - 4]);
                mma_tf32(S[2 * jp],     Qa[kd][0], Qa[kd][1], Qa[kd][2], Qa[kd][3], b0a, b1a);
                mma_tf32(S[2 * jp + 1], Qa[kd][0], Qa[kd][1], Qa[kd][2], Qa[kd][3], b0b, b1b);
            }
        }

        // Online softmax (log2 domain; scale applied here)
        float mx0 = -1e30f, mx1 = -1e30f;
#pragma unroll
        for (int jn = 0; jn < 8; jn++) {
            S[jn][0] *= sc; S[jn][1] *= sc; S[jn][2] *= sc; S[jn][3] *= sc;
            mx0 = fmaxf(mx0, fmaxf(S[jn][0], S[jn][1]));
            mx1 = fmaxf(mx1, fmaxf(S[jn][2], S[jn][3]));
        }
        mx0 = fmaxf(mx0, __shfl_xor_sync(0xffffffffu, mx0, 1));
        mx0 = fmaxf(mx0, __shfl_xor_sync(0xffffffffu, mx0, 2));
        mx1 = fmaxf(mx1, __shfl_xor_sync(0xffffffffu, mx1, 1));
        mx1 = fmaxf(mx1, __shfl_xor_sync(0xffffffffu, mx1, 2));
        float mn0 = fmaxf(m0, mx0), mn1 = fmaxf(m1, mx1);
        float al0 = ex2f(m0 - mn0), al1 = ex2f(m1 - mn1);
        float s0 = 0.f, s1 = 0.f;
#pragma unroll
        for (int jn = 0; jn < 8; jn++) {
            S[jn][0] = ex2f(S[jn][0] - mn0); s0 += S[jn][0];
            S[jn][1] = ex2f(S[jn][1] - mn0); s0 += S[jn][1];
            S[jn][2] = ex2f(S[jn][2] - mn1); s1 += S[jn][2];
            S[jn][3] = ex2f(S[jn][3] - mn1); s1 += S[jn][3];
        }
        s0 += __shfl_xor_sync(0xffffffffu, s0, 1);
        s0 += __shfl_xor_sync(0xffffffffu, s0, 2);
        s1 += __shfl_xor_sync(0xffffffffu, s1, 1);
        s1 += __shfl_xor_sync(0xffffffffu, s1, 2);
        l0 = l0 * al0 + s0; m0 = mn0;
        l1 = l1 * al1 + s1; m1 = mn1;
#pragma unroll
        for (int dn = 0; dn < 8; dn++) {
            Oacc[dn][0] *= al0; Oacc[dn][1] *= al0;
            Oacc[dn][2] *= al1; Oacc[dn][3] *= al1;
        }

        // P: c-layout -> a-layout via shuffles (in place), cvt to tf32
        const int srcA = (lane & ~3) | (tg >> 1);
        const int srcB = srcA | 2;
        const bool odd = (tg & 1);
#pragma unroll
        for (int kj = 0; kj < 8; kj++) {
            float x0 = __shfl_sync(0xffffffffu, S[kj][0], srcA);
            float x1 = __shfl_sync(0xffffffffu, S[kj][1], srcA);
            float y0 = __shfl_sync(0xffffffffu, S[kj][0], srcB);
            float y1 = __shfl_sync(0xffffffffu, S[kj][1], srcB);
            float z0 = __shfl_sync(0xffffffffu, S[kj][2], srcA);
            float z1 = __shfl_sync(0xffffffffu, S[kj][3], srcA);
            float w0 = __shfl_sync(0xffffffffu, S[kj][2], srcB);
            float w1 = __shfl_sync(0xffffffffu, S[kj][3], srcB);
            S[kj][0] = cvt_tf32(odd ? x1 : x0);
            S[kj][2] = cvt_tf32(odd ? y1 : y0);
            S[kj][1] = cvt_tf32(odd ? z1 : z0);
            S[kj][3] = cvt_tf32(odd ? w1 : w0);
        }

        // O += P @ V
#pragma unroll
        for (int dp = 0; dp < 4; dp++) {
            const float* rv0 = Vs + (dp * 16 + g) * LQ;
            const float* rv1 = rv0 + 8 * LQ;
            float4 A0 = *(const float4*)(rv0 + tg * 8);
            float4 A1 = *(const float4*)(rv0 + tg * 8 + 4);
            float4 A2 = *(const float4*)(rv0 + (tg + 4) * 8);
            float4 A3 = *(const float4*)(rv0 + (tg + 4) * 8 + 4);
            float4 B0 = *(const float4*)(rv1 + tg * 8);
            float4 B1 = *(const float4*)(rv1 + tg * 8 + 4);
            float4 B2 = *(const float4*)(rv1 + (tg + 4) * 8);
            float4 B3 = *(const float4*)(rv1 + (tg + 4) * 8 + 4);
#pragma unroll
            for (int kj = 0; kj < 8; kj++) {
                uint32_t a0 = __float_as_uint(S[kj][0]);
                uint32_t a1 = __float_as_uint(S[kj][1]);
                uint32_t a2 = __float_as_uint(S[kj][2]);
                uint32_t a3 = __float_as_uint(S[kj][3]);
                uint32_t b0a = __float_as_uint(kj < 4 ? (&A0.x)[kj] : (&A1.x)[kj - 4]);
                uint32_t b1a = __float_as_uint(kj < 4 ? (&A2.x)[kj] : (&A3.x)[kj - 4]);
                uint32_t b0b = __float_as_uint(kj < 4 ? (&B0.x)[kj] : (&B1.x)[kj - 4]);
                uint32_t b1b = __float_as_uint(kj < 4 ? (&B2.x)[kj] : (&B3.x)[kj - 4]);
                mma_tf32(Oacc[2 * dp],     a0, a1, a2, a3, b0a, b1a);
                mma_tf32(Oacc[2 * dp + 1], a0, a1, a2, a3, b0b, b1b);
            }
        }
        __syncthreads();
    }

    // Epilogue: write k-permuted + cvt for proj GEMM
    float inv0 = 1.f / l0, inv1 = 1.f / l1;
    int r0 = q0 + warp * 16 + g;
#pragma unroll
    for (int dn = 0; dn < 8; dn++) {
        int C0 = h * HD + dn * 8 + 2 * tg;
        int w0 = C0 & 31;
        int pc0 = (C0 & ~31) + (w0 & 3) * 8 + (w0 >> 2);
        float* o0 = out + ((size_t)b * SEQ + r0) * DIM;
        float* o1 = out + ((size_t)b * SEQ + r0 + 8) * DIM;
        o0[pc0]     = cvt_tf32(Oacc[dn][0] * inv0);
        o0[pc0 + 8] = cvt_tf32(Oacc[dn][1] * inv0);
        o1[pc0]     = cvt_tf32(Oacc[dn][2] * inv1);
        o1[pc0 + 8] = cvt_tf32(Oacc[dn][3] * inv1);
    }
}

// ---------------------------------------------------------------------------
extern "C" void kernel_launch(void* const* d_in, const int* in_sizes, int n_in,
                              void* d_out, int out_size)
{
    const float* x      = (const float*)d_in[0];
    const float* qkv_w  = (const float*)d_in[1];
    const float* qkv_b  = (const float*)d_in[2];
    const float* proj_w = (const float*)d_in[3];
    const float* proj_b = (const float*)d_in[4];
    const float* qn_g   = (const float*)d_in[5];
    const float* qn_b   = (const float*)d_in[6];
    float* out = (float*)d_out;

    float *qkv, *attn, *xP, *wqP, *wpP, *kP, *vP;
    cudaGetSymbolAddress((void**)&qkv,  g_qkv);
    cudaGetSymbolAddress((void**)&attn, g_attn);
    cudaGetSymbolAddress((void**)&xP,   g_xP);
    cudaGetSymbolAddress((void**)&wqP,  g_wqP);
    cudaGetSymbolAddress((void**)&wpP,  g_wpP);
    cudaGetSymbolAddress((void**)&kP,   g_kP);
    cudaGetSymbolAddress((void**)&vP,   g_vP);

    // 0) permute+cvt inputs
    permute32_cvt<<<TOKENS * DIM / 4 / 256, 256>>>(x, xP, DIM);
    permute32_cvt<<<QKV_N * DIM / 4 / 256, 256>>>(qkv_w, wqP, DIM);
    permute32_cvt<<<DIM * DIM / 4 / 256, 256>>>(proj_w, wpP, DIM);

    // 1) QKV projection (plain fp32 out)
    sgemm_tf32p<<<dim3(QKV_N / 128, TOKENS / 128), 256>>>(
        xP, wqP, qkv_b, qkv, TOKENS, QKV_N, DIM);

    // 2) LayerNorm q (in place, permuted) and k (-> kP, permuted)
    qk_layernorm_p<<<TOKENS * 2 * NHEAD * 32 / 256, 256>>>(qkv, kP, qn_g, qn_b);

    // 3) V transpose (-> vP, permuted)
    v_transpose_p<<<BATCH * NHEAD * 16 * 4, 256>>>(qkv, vP);

    // 4) Attention (-> attn, permuted tf32)
    attn_tf32p<<<dim3(SEQ / 64, BATCH * NHEAD), 128>>>(qkv, kP, vP, attn);

    // 5) Output projection (plain fp32 out + bias)
    sgemm_tf32p<<<dim3(DIM / 128, TOKENS / 128), 256>>>(
        attn, wpP, proj_b, out, TOKENS, DIM, DIM);
}

// round 4
// speedup vs baseline: 2.6718x; 2.6718x over previous
#include <cuda_runtime.h>
#include <cuda_fp16.h>
#include <stdint.h>

#define DIM 768
#define NHEAD 12
#define HD 64
#define BATCH 8
#define SEQ 1024
#define TOKENS (BATCH*SEQ)   // 8192
#define QKV_N (3*DIM)        // 2304

// Scratch (no allocation allowed)
__device__ __half g_xH  [TOKENS * DIM];     // x in fp16
__device__ __half g_wqH [QKV_N * DIM];      // qkv_w fp16
__device__ __half g_wpH [DIM * DIM];        // proj_w fp16
__device__ __half g_qkvH[TOKENS * QKV_N];   // qkv fp16 (q,k LayerNormed in place)
__device__ __half g_attnH[TOKENS * DIM];    // attention out fp16

__device__ __forceinline__ float ex2f(float x) {
    float r; asm("ex2.approx.f32 %0, %1;\n" : "=f"(r) : "f"(x)); return r;
}
__device__ __forceinline__ uint32_t smem_u32(const void* p) {
    return (uint32_t)__cvta_generic_to_shared(p);
}
__device__ __forceinline__ void ldsm4(uint32_t& r0, uint32_t& r1, uint32_t& r2,
                                      uint32_t& r3, uint32_t a) {
    asm volatile("ldmatrix.sync.aligned.m8n8.x4.shared.b16 {%0,%1,%2,%3},[%4];"
                 : "=r"(r0), "=r"(r1), "=r"(r2), "=r"(r3) : "r"(a));
}
__device__ __forceinline__ void ldsm4t(uint32_t& r0, uint32_t& r1, uint32_t& r2,
                                       uint32_t& r3, uint32_t a) {
    asm volatile("ldmatrix.sync.aligned.m8n8.x4.trans.shared.b16 {%0,%1,%2,%3},[%4];"
                 : "=r"(r0), "=r"(r1), "=r"(r2), "=r"(r3) : "r"(a));
}
__device__ __forceinline__ void mma16816(float c[4],
    uint32_t a0, uint32_t a1, uint32_t a2, uint32_t a3, uint32_t b0, uint32_t b1)
{
    asm volatile(
        "mma.sync.aligned.m16n8k16.row.col.f32.f16.f16.f32 "
        "{%0,%1,%2,%3},{%4,%5,%6,%7},{%8,%9},{%0,%1,%2,%3};"
        : "+f"(c[0]), "+f"(c[1]), "+f"(c[2]), "+f"(c[3])
        : "r"(a0), "r"(a1), "r"(a2), "r"(a3), "r"(b0), "r"(b1));
}
__device__ __forceinline__ uint32_t packh2(float x, float y) {
    __half2 h = __floats2half2_rn(x, y);
    return *reinterpret_cast<uint32_t*>(&h);
}

// ---------------------------------------------------------------------------
// fp32 -> fp16 conversion, 8 elements per thread
// ---------------------------------------------------------------------------
__global__ __launch_bounds__(256) void cvt_f2h(
    const float* __restrict__ in, __half* __restrict__ out, int n)
{
    int i = blockIdx.x * 256 + threadIdx.x;
    if (i * 8 >= n) return;
    float4 a = ((const float4*)in)[2 * i];
    float4 b = ((const float4*)in)[2 * i + 1];
    uint4 o;
    o.x = packh2(a.x, a.y); o.y = packh2(a.z, a.w);
    o.z = packh2(b.x, b.y); o.w = packh2(b.z, b.w);
    ((uint4*)out)[i] = o;
}

// ---------------------------------------------------------------------------
// fp16 GEMM via mma.m16n8k16 + ldmatrix: C[m][n] = sum_k A[m][k]*W[n][k] + b[n]
// A:[M][K], W:[N][K] fp16 row-major. BM=BN=128, BK=32, 256 thr (8 warps 2x4),
// warp tile 64x32. Double-buffered swizzled smem (chunk ^ ((row>>1)&3)),
// one __syncthreads per BK.  HALF_OUT selects fp16 vs fp32 output.
// ---------------------------------------------------------------------------
template<bool HALF_OUT>
__global__ __launch_bounds__(256, 2) void hgemm_bias(
    const __half* __restrict__ A, const __half* __restrict__ W,
    const float* __restrict__ bias, void* __restrict__ Cout,
    int M, int N, int K)
{
    __shared__ __align__(16) unsigned char smA[2 * 8192];
    __shared__ __align__(16) unsigned char smW[2 * 8192];

    const int bm = blockIdx.y * 128, bn = blockIdx.x * 128;
    const int t = threadIdx.x, lane = t & 31, warp = t >> 5;
    const int wm = (warp & 1) * 64, wn = (warp >> 1) * 32;
    const int g = lane >> 2, tg = lane & 3;

    // store side: thread owns chunks s=t and s=t+256 (row = s>>2, c = s&3)
    const int c_st = t & 3;
    const int row0 = t >> 2, row1 = row0 + 64;
    const int so0 = row0 * 64 + ((c_st ^ ((row0 >> 1) & 3)) * 16);
    const int so1 = row1 * 64 + ((c_st ^ ((row1 >> 1) & 3)) * 16);

    // frag addresses
    const int ra = (lane & 7) + 8 * ((lane >> 3) & 1), ca = lane >> 4;
    const int rb = (lane & 7) + 8 * (lane >> 4),       cb = (lane >> 3) & 1;
    int aoff[4][2], woff[2][2];
#pragma unroll
    for (int im = 0; im < 4; im++) {
        int m = wm + 16 * im + ra;
#pragma unroll
        for (int h = 0; h < 2; h++)
            aoff[im][h] = m * 64 + (((2 * h + ca) ^ ((m >> 1) & 3)) * 16);
    }
#pragma unroll
    for (int u = 0; u < 2; u++) {
        int n = wn + 16 * u + rb;
#pragma unroll
        for (int h = 0; h < 2; h++)
            woff[u][h] = n * 64 + (((2 * h + cb) ^ ((n >> 1) & 3)) * 16);
    }
    const uint32_t aB = smem_u32(smA), wB = smem_u32(smW);

    float acc[4][4][4];
#pragma unroll
    for (int i = 0; i < 4; i++)
#pragma unroll
        for (int j = 0; j < 4; j++)
#pragma unroll
            for (int c = 0; c < 4; c++) acc[i][j][c] = 0.f;

    const __half* Ap0 = A + (size_t)(bm + row0) * K + c_st * 8;
    const __half* Ap1 = A + (size_t)(bm + row1) * K + c_st * 8;
    const __half* Wp0 = W + (size_t)(bn + row0) * K + c_st * 8;
    const __half* Wp1 = W + (size_t)(bn + row1) * K + c_st * 8;

    uint4 pa0 = *(const uint4*)(Ap0), pa1 = *(const uint4*)(Ap1);
    uint4 pw0 = *(const uint4*)(Wp0), pw1 = *(const uint4*)(Wp1);

    int buf = 0;
    for (int k0 = 0; k0 < K; k0 += 32) {
        *(uint4*)(smA + buf * 8192 + so0) = pa0;
        *(uint4*)(smA + buf * 8192 + so1) = pa1;
        *(uint4*)(smW + buf * 8192 + so0) = pw0;
        *(uint4*)(smW + buf * 8192 + so1) = pw1;
        __syncthreads();

        if (k0 + 32 < K) {
            pa0 = *(const uint4*)(Ap0 + k0 + 32);
            pa1 = *(const uint4*)(Ap1 + k0 + 32);
            pw0 = *(const uint4*)(Wp0 + k0 + 32);
            pw1 = *(const uint4*)(Wp1 + k0 + 32);
        }

        const uint32_t aBb = aB + buf * 8192, wBb = wB + buf * 8192;
#pragma unroll
        for (int h = 0; h < 2; h++) {
            uint32_t a[4][4], bb[4][2];
#pragma unroll
            for (int im = 0; im < 4; im++)
                ldsm4(a[im][0], a[im][1], a[im][2], a[im][3], aBb + aoff[im][h]);
#pragma unroll
            for (int u = 0; u < 2; u++)
                ldsm4(bb[2 * u][0], bb[2 * u][1], bb[2 * u + 1][0], bb[2 * u + 1][1],
                      wBb + woff[u][h]);
#pragma unroll
            for (int im = 0; im < 4; im++)
#pragma unroll
                for (int jn = 0; jn < 4; jn++)
                    mma16816(acc[im][jn], a[im][0], a[im][1], a[im][2], a[im][3],
                             bb[jn][0], bb[jn][1]);
        }
        buf ^= 1;
    }

#pragma unroll
    for (int im = 0; im < 4; im++) {
        int r0 = bm + wm + 16 * im + g;
#pragma unroll
        for (int jn = 0; jn < 4; jn++) {
            int c0 = bn + wn + 8 * jn + 2 * tg;
            float bx = bias[c0], by = bias[c0 + 1];
            float v0 = acc[im][jn][0] + bx, v1 = acc[im][jn][1] + by;
            float v2 = acc[im][jn][2] + bx, v3 = acc[im][jn][3] + by;
            if (HALF_OUT) {
                __half* C = (__half*)Cout;
                *(uint32_t*)(C + (size_t)r0 * N + c0) = packh2(v0, v1);
                *(uint32_t*)(C + (size_t)(r0 + 8) * N + c0) = packh2(v2, v3);
            } else {
                float* C = (float*)Cout;
                *(float2*)(C + (size_t)r0 * N + c0) = make_float2(v0, v1);
                *(float2*)(C + (size_t)(r0 + 8) * N + c0) = make_float2(v2, v3);
            }
        }
    }
}

// ---------------------------------------------------------------------------
// LayerNorm over each 64-wide head segment of q and k, in place, fp16 I/O.
// One warp per (token, part, head).
// ---------------------------------------------------------------------------
__global__ __launch_bounds__(256) void qk_ln_h(
    __half* __restrict__ qkv, const float* __restrict__ gamma,
    const float* __restrict__ beta)
{
    int gw = (blockIdx.x * 256 + threadIdx.x) >> 5;
    int lane = threadIdx.x & 31;
    int h = gw % NHEAD;
    int tmp = gw / NHEAD;
    int p = tmp & 1;
    int m = tmp >> 1;
    if (m >= TOKENS) return;

    __half* row = qkv + (size_t)m * QKV_N + p * DIM + h * HD;
    float2 v = __half22float2(*(__half2*)(row + lane * 2));

    float s = v.x + v.y;
#pragma unroll
    for (int o = 16; o; o >>= 1) s += __shfl_xor_sync(0xffffffffu, s, o);
    float mu = s * (1.f / 64.f);
    float dx = v.x - mu, dy = v.y - mu;
    float vs = dx * dx + dy * dy;
#pragma unroll
    for (int o = 16; o; o >>= 1) vs += __shfl_xor_sync(0xffffffffu, vs, o);
    float rstd = rsqrtf(vs * (1.f / 64.f) + 1e-5f);

    float r0 = dx * rstd * gamma[lane * 2 + 0] + beta[lane * 2 + 0];
    float r1 = dy * rstd * gamma[lane * 2 + 1] + beta[lane * 2 + 1];
    *(__half2*)(row + lane * 2) = __floats2half2_rn(r0, r1);
}

// ---------------------------------------------------------------------------
// Flash attention, fp16 mma m16n8k16 + ldmatrix. 128 threads = 4 warps,
// q-tile 64 (warp w: rows 16w..16w+15). V read row-major via ldmatrix.trans.
// P reuses the S c-fragment layout directly (no shuffles). Out fp16.
// smem rows 128B, swizzle chunk ^ (row&7).
// ---------------------------------------------------------------------------
__global__ __launch_bounds__(128) void attn_h(
    const __half* __restrict__ qkv, __half* __restrict__ out)
{
    __shared__ __align__(16) unsigned char sK[64 * 128];
    __shared__ __align__(16) unsigned char sV[64 * 128];

    const int q0 = blockIdx.x * 64;
    const int bh = blockIdx.y;
    const int b = bh / NHEAD, h = bh % NHEAD;
    const int t = threadIdx.x, lane = t & 31, warp = t >> 5;
    const int g = lane >> 2, tg = lane & 3;
    const uint32_t kB = smem_u32(sK), vB = smem_u32(sV);
    const float sc = 0.125f * 1.4426950408889634f;

    const int ra = (lane & 7) + 8 * ((lane >> 3) & 1), ca = lane >> 4;
    const int rb = (lane & 7) + 8 * (lane >> 4),       cb = (lane >> 3) & 1;

    // store side: 4 chunks per thread: s = t + l*128 -> row = s>>3, c = s&7
    int srow[4], scol[4], soff[4];
#pragma unroll
    for (int l = 0; l < 4; l++) {
        int s = t + l * 128;
        srow[l] = s >> 3; scol[l] = s & 7;
        soff[l] = srow[l] * 128 + ((scol[l] ^ (srow[l] & 7)) * 16);
    }

    // Stage Q through sK, grab A-fragments
    {
        const __half* qg = qkv + ((size_t)(b * SEQ + q0)) * QKV_N + h * HD;
#pragma unroll
        for (int l = 0; l < 4; l++)
            *(uint4*)(sK + soff[l]) =
                *(const uint4*)(qg + (size_t)srow[l] * QKV_N + scol[l] * 8);
    }
    __syncthreads();
    uint32_t Qa[4][4];
    {
        int m = 16 * warp + ra;
#pragma unroll
        for (int kd = 0; kd < 4; kd++)
            ldsm4(Qa[kd][0], Qa[kd][1], Qa[kd][2], Qa[kd][3],
                  kB + m * 128 + (((2 * kd + ca) ^ (m & 7)) * 16));
    }
    __syncthreads();

    float Oacc[8][4];
#pragma unroll
    for (int dn = 0; dn < 8; dn++)
#pragma unroll
        for (int c = 0; c < 4; c++) Oacc[dn][c] = 0.f;
    float m0 = -1e30f, m1 = -1e30f, l0 = 0.f, l1 = 0.f;

    // frag offsets
    int koff[4][4];   // [u][kd]: K b-frag, rows 16u+rb, chunk 2kd+cb
#pragma unroll
    for (int u = 0; u < 4; u++) {
        int n = 16 * u + rb;
#pragma unroll
        for (int kd = 0; kd < 4; kd++)
            koff[u][kd] = n * 128 + (((2 * kd + cb) ^ (n & 7)) * 16);
    }
    int voff[4][4];   // [kt][dp]: V trans frag, rows 16kt+ra, chunk 2dp+ca
#pragma unroll
    for (int kt = 0; kt < 4; kt++) {
        int j = 16 * kt + ra;
#pragma unroll
        for (int dp = 0; dp < 4; dp++)
            voff[kt][dp] = j * 128 + (((2 * dp + ca) ^ (j & 7)) * 16);
    }

    for (int kv = 0; kv < SEQ; kv += 64) {
        const __half* kg = qkv + ((size_t)(b * SEQ + kv)) * QKV_N + DIM + h * HD;
        const __half* vg = kg + DIM;
#pragma unroll
        for (int l = 0; l < 4; l++) {
            *(uint4*)(sK + soff[l]) =
                *(const uint4*)(kg + (size_t)srow[l] * QKV_N + scol[l] * 8);
            *(uint4*)(sV + soff[l]) =
                *(const uint4*)(vg + (size_t)srow[l] * QKV_N + scol[l] * 8);
        }
        __syncthreads();

        // S = Q @ K^T
        float S[8][4];
#pragma unroll
        for (int jn = 0; jn < 8; jn++)
#pragma unroll
            for (int c = 0; c < 4; c++) S[jn][c] = 0.f;
#pragma unroll
        for (int kd = 0; kd < 4; kd++) {
#pragma unroll
            for (int u = 0; u < 4; u++) {
                uint32_t b0a, b1a, b0b, b1b;
                ldsm4(b0a, b1a, b0b, b1b, kB + koff[u][kd]);
                mma16816(S[2 * u],     Qa[kd][0], Qa[kd][1], Qa[kd][2], Qa[kd][3], b0a, b1a);
                mma16816(S[2 * u + 1], Qa[kd][0], Qa[kd][1], Qa[kd][2], Qa[kd][3], b0b, b1b);
            }
        }

        // Online softmax in log2 domain
        float mx0 = -1e30f, mx1 = -1e30f;
#pragma unroll
        for (int jn = 0; jn < 8; jn++) {
            S[jn][0] *= sc; S[jn][1] *= sc; S[jn][2] *= sc; S[jn][3] *= sc;
            mx0 = fmaxf(mx0, fmaxf(S[jn][0], S[jn][1]));
            mx1 = fmaxf(mx1, fmaxf(S[jn][2], S[jn][3]));
        }
        mx0 = fmaxf(mx0, __shfl_xor_sync(0xffffffffu, mx0, 1));
        mx0 = fmaxf(mx0, __shfl_xor_sync(0xffffffffu, mx0, 2));
        mx1 = fmaxf(mx1, __shfl_xor_sync(0xffffffffu, mx1, 1));
        mx1 = fmaxf(mx1, __shfl_xor_sync(0xffffffffu, mx1, 2));
        float mn0 = fmaxf(m0, mx0), mn1 = fmaxf(m1, mx1);
        float al0 = ex2f(m0 - mn0), al1 = ex2f(m1 - mn1);
        float s0 = 0.f, s1 = 0.f;
#pragma unroll
        for (int jn = 0; jn < 8; jn++) {
            S[jn][0] = ex2f(S[jn][0] - mn0); s0 += S[jn][0];
            S[jn][1] = ex2f(S[jn][1] - mn0); s0 += S[jn][1];
            S[jn][2] = ex2f(S[jn][2] - mn1); s1 += S[jn][2];
            S[jn][3] = ex2f(S[jn][3] - mn1); s1 += S[jn][3];
        }
        s0 += __shfl_xor_sync(0xffffffffu, s0, 1);
        s0 += __shfl_xor_sync(0xffffffffu, s0, 2);
        s1 += __shfl_xor_sync(0xffffffffu, s1, 1);
        s1 += __shfl_xor_sync(0xffffffffu, s1, 2);
        l0 = l0 * al0 + s0; m0 = mn0;
        l1 = l1 * al1 + s1; m1 = mn1;
#pragma unroll
        for (int dn = 0; dn < 8; dn++) {
            Oacc[dn][0] *= al0; Oacc[dn][1] *= al0;
            Oacc[dn][2] *= al1; Oacc[dn][3] *= al1;
        }

        // P a-fragments directly from S layout (pack to fp16)
        uint32_t Pa[4][4];
#pragma unroll
        for (int kt = 0; kt < 4; kt++) {
            Pa[kt][0] = packh2(S[2 * kt][0],     S[2 * kt][1]);
            Pa[kt][1] = packh2(S[2 * kt][2],     S[2 * kt][3]);
            Pa[kt][2] = packh2(S[2 * kt + 1][0], S[2 * kt + 1][1]);
            Pa[kt][3] = packh2(S[2 * kt + 1][2], S[2 * kt + 1][3]);
        }

        // O += P @ V  (V b-fragments via ldmatrix.trans, row-major V)
#pragma unroll
        for (int kt = 0; kt < 4; kt++) {
#pragma unroll
            for (int dp = 0; dp < 4; dp++) {
                uint32_t b0a, b1a, b0b, b1b;
                ldsm4t(b0a, b1a, b0b, b1b, vB + voff[kt][dp]);
                mma16816(Oacc[2 * dp],     Pa[kt][0], Pa[kt][1], Pa[kt][2], Pa[kt][3], b0a, b1a);
                mma16816(Oacc[2 * dp + 1], Pa[kt][0], Pa[kt][1], Pa[kt][2], Pa[kt][3], b0b, b1b);
            }
        }
        __syncthreads();
    }

    // Epilogue: fp16 out
    float inv0 = 1.f / l0, inv1 = 1.f / l1;
    int r0 = q0 + 16 * warp + g;
    __half* o0 = out + ((size_t)b * SEQ + r0) * DIM + h * HD;
    __half* o1 = o0 + 8 * DIM;
#pragma unroll
    for (int dn = 0; dn < 8; dn++) {
        int c0 = 8 * dn + 2 * tg;
        *(uint32_t*)(o0 + c0) = packh2(Oacc[dn][0] * inv0, Oacc[dn][1] * inv0);
        *(uint32_t*)(o1 + c0) = packh2(Oacc[dn][2] * inv1, Oacc[dn][3] * inv1);
    }
}

// ---------------------------------------------------------------------------
extern "C" void kernel_launch(void* const* d_in, const int* in_sizes, int n_in,
                              void* d_out, int out_size)
{
    const float* x      = (const float*)d_in[0];
    const float* qkv_w  = (const float*)d_in[1];
    const float* qkv_b  = (const float*)d_in[2];
    const float* proj_w = (const float*)d_in[3];
    const float* proj_b = (const float*)d_in[4];
    const float* qn_g   = (const float*)d_in[5];
    const float* qn_b   = (const float*)d_in[6];
    float* out = (float*)d_out;

    __half *xH, *wqH, *wpH, *qkvH, *attnH;
    cudaGetSymbolAddress((void**)&xH,    g_xH);
    cudaGetSymbolAddress((void**)&wqH,   g_wqH);
    cudaGetSymbolAddress((void**)&wpH,   g_wpH);
    cudaGetSymbolAddress((void**)&qkvH,  g_qkvH);
    cudaGetSymbolAddress((void**)&attnH, g_attnH);

    // 0) fp32 -> fp16 conversions
    cvt_f2h<<<TOKENS * DIM / 2048, 256>>>(x, xH, TOKENS * DIM);
    cvt_f2h<<<QKV_N * DIM / 2048, 256>>>(qkv_w, wqH, QKV_N * DIM);
    cvt_f2h<<<DIM * DIM / 2048, 256>>>(proj_w, wpH, DIM * DIM);

    // 1) QKV projection (fp16 out)
    hgemm_bias<true><<<dim3(QKV_N / 128, TOKENS / 128), 256>>>(
        xH, wqH, qkv_b, qkvH, TOKENS, QKV_N, DIM);

    // 2) LayerNorm q,k in place
    qk_ln_h<<<TOKENS * 2 * NHEAD * 32 / 256, 256>>>(qkvH, qn_g, qn_b);

    // 3) Attention (fp16 out)
    attn_h<<<dim3(SEQ / 64, BATCH * NHEAD), 128>>>(qkvH, attnH);

    // 4) Output projection (fp32 out)
    hgemm_bias<false><<<dim3(DIM / 128, TOKENS / 128), 256>>>(
        attnH, wpH, proj_b, out, TOKENS, DIM, DIM);
}

// round 6
// speedup vs baseline: 2.9849x; 1.1172x over previous
#include <cuda_runtime.h>
#include <cuda_fp16.h>
#include <stdint.h>

#define DIM 768
#define NHEAD 12
#define HD 64
#define BATCH 8
#define SEQ 1024
#define TOKENS (BATCH*SEQ)   // 8192
#define QKV_N (3*DIM)        // 2304

// Scratch (no allocation allowed)
__device__ __half g_xH  [TOKENS * DIM];
__device__ __half g_wqH [QKV_N * DIM];
__device__ __half g_wpH [DIM * DIM];
__device__ __half g_qkvH[TOKENS * QKV_N];
__device__ __half g_attnH[TOKENS * DIM];

__device__ __forceinline__ float ex2f(float x) {
    float r; asm("ex2.approx.f32 %0, %1;\n" : "=f"(r) : "f"(x)); return r;
}
__device__ __forceinline__ uint32_t smem_u32(const void* p) {
    return (uint32_t)__cvta_generic_to_shared(p);
}
__device__ __forceinline__ uint32_t packh2(float x, float y) {
    __half2 h = __floats2half2_rn(x, y);
    return *reinterpret_cast<uint32_t*>(&h);
}
__device__ __forceinline__ void ldsm4(uint32_t& r0, uint32_t& r1, uint32_t& r2,
                                      uint32_t& r3, uint32_t a) {
    asm volatile("ldmatrix.sync.aligned.m8n8.x4.shared.b16 {%0,%1,%2,%3},[%4];"
                 : "=r"(r0), "=r"(r1), "=r"(r2), "=r"(r3) : "r"(a));
}
__device__ __forceinline__ void ldsm4t(uint32_t& r0, uint32_t& r1, uint32_t& r2,
                                       uint32_t& r3, uint32_t a) {
    asm volatile("ldmatrix.sync.aligned.m8n8.x4.trans.shared.b16 {%0,%1,%2,%3},[%4];"
                 : "=r"(r0), "=r"(r1), "=r"(r2), "=r"(r3) : "r"(a));
}
__device__ __forceinline__ void mma16816(float c[4],
    uint32_t a0, uint32_t a1, uint32_t a2, uint32_t a3, uint32_t b0, uint32_t b1)
{
    asm volatile(
        "mma.sync.aligned.m16n8k16.row.col.f32.f16.f16.f32 "
        "{%0,%1,%2,%3},{%4,%5,%6,%7},{%8,%9},{%0,%1,%2,%3};"
        : "+f"(c[0]), "+f"(c[1]), "+f"(c[2]), "+f"(c[3])
        : "r"(a0), "r"(a1), "r"(a2), "r"(a3), "r"(b0), "r"(b1));
}
__device__ __forceinline__ void cp16(uint32_t dst, const void* src) {
    asm volatile("cp.async.cg.shared.global [%0], [%1], 16;\n" :: "r"(dst), "l"(src));
}
__device__ __forceinline__ void cp_commit() {
    asm volatile("cp.async.commit_group;\n" ::: "memory");
}
template<int N> __device__ __forceinline__ void cp_wait() {
    asm volatile("cp.async.wait_group %0;\n" :: "n"(N) : "memory");
}

// ---------------------------------------------------------------------------
// fp32 -> fp16 conversion
// ---------------------------------------------------------------------------
__global__ __launch_bounds__(256) void cvt_f2h(
    const float* __restrict__ in, __half* __restrict__ out, int n)
{
    int i = blockIdx.x * 256 + threadIdx.x;
    if (i * 8 >= n) return;
    float4 a = ((const float4*)in)[2 * i];
    float4 b = ((const float4*)in)[2 * i + 1];
    uint4 o;
    o.x = packh2(a.x, a.y); o.y = packh2(a.z, a.w);
    o.z = packh2(b.x, b.y); o.w = packh2(b.z, b.w);
    ((uint4*)out)[i] = o;
}

// ---------------------------------------------------------------------------
// fp16 GEMM, mma.m16n8k16: C[m][n] = sum_k A[m][k]*W[n][k] + bias[n]
// 128x128 block, 4 warps (2x2 of 64x64 warp tiles), BK=32, 3-stage cp.async.
// smem rows of 32 halves (64B), swizzle chunk ^ ((row>>1)&3).
// ---------------------------------------------------------------------------
#define GSTAGES 3
template<bool HALF_OUT>
__global__ __launch_bounds__(128, 2) void hgemm2(
    const __half* __restrict__ A, const __half* __restrict__ W,
    const float* __restrict__ bias, void* __restrict__ Cout,
    int M, int N, int K)
{
    __shared__ __align__(16) unsigned char sm[GSTAGES * 16384];

    const int bm = blockIdx.y * 128, bn = blockIdx.x * 128;
    const int t = threadIdx.x, lane = t & 31, warp = t >> 5;
    const int wm = (warp & 1) * 64, wn = (warp >> 1) * 64;
    const int g = lane >> 2, tg = lane & 3;
    const int ra = (lane & 7) + 8 * ((lane >> 3) & 1), ca = lane >> 4;
    const int rb = (lane & 7) + 8 * (lane >> 4),       cb = (lane >> 3) & 1;
    const uint32_t sbase = smem_u32(sm);

    // store slots: l=0..3: s=t+l*128 -> row=s>>2 (0..127), c=s&3
    uint32_t swo[4];
    const __half* ag[4];
    const __half* wg[4];
#pragma unroll
    for (int l = 0; l < 4; l++) {
        int s = t + l * 128, r = s >> 2, c = s & 3;
        swo[l] = (uint32_t)(r * 64 + ((c ^ ((r >> 1) & 3)) * 16));
        ag[l] = A + (size_t)(bm + r) * K + c * 8;
        wg[l] = W + (size_t)(bn + r) * K + c * 8;
    }

    const int nchunk = K >> 5;
    // prologue: stages 0,1
#pragma unroll
    for (int c = 0; c < 2; c++) {
        uint32_t ab = sbase + c * 16384;
#pragma unroll
        for (int l = 0; l < 4; l++) cp16(ab + swo[l], ag[l] + c * 32);
#pragma unroll
        for (int l = 0; l < 4; l++) cp16(ab + 8192 + swo[l], wg[l] + c * 32);
        cp_commit();
    }

    float acc[4][8][4];
#pragma unroll
    for (int i = 0; i < 4; i++)
#pragma unroll
        for (int j = 0; j < 8; j++)
#pragma unroll
            for (int c = 0; c < 4; c++) acc[i][j][c] = 0.f;

    for (int c = 0; c < nchunk; c++) {
        cp_wait<1>();
        __syncthreads();
        const uint32_t ab = sbase + (c % GSTAGES) * 16384;
#pragma unroll
        for (int h = 0; h < 2; h++) {
            uint32_t a[4][4], bf[8][2];
#pragma unroll
            for (int im = 0; im < 4; im++) {
                int m = wm + 16 * im + ra;
                ldsm4(a[im][0], a[im][1], a[im][2], a[im][3],
                      ab + m * 64 + (((2 * h + ca) ^ ((m >> 1) & 3)) * 16));
            }
#pragma unroll
            for (int u = 0; u < 4; u++) {
                int n = wn + 16 * u + rb;
                ldsm4(bf[2 * u][0], bf[2 * u][1], bf[2 * u + 1][0], bf[2 * u + 1][1],
                      ab + 8192 + n * 64 + (((2 * h + cb) ^ ((n >> 1) & 3)) * 16));
            }
#pragma unroll
            for (int im = 0; im < 4; im++)
#pragma unroll
                for (int jn = 0; jn < 8; jn++)
                    mma16816(acc[im][jn], a[im][0], a[im][1], a[im][2], a[im][3],
                             bf[jn][0], bf[jn][1]);
        }
        int pf = c + 2;
        if (pf < nchunk) {
            uint32_t ab2 = sbase + (pf % GSTAGES) * 16384;
#pragma unroll
            for (int l = 0; l < 4; l++) cp16(ab2 + swo[l], ag[l] + pf * 32);
#pragma unroll
            for (int l = 0; l < 4; l++) cp16(ab2 + 8192 + swo[l], wg[l] + pf * 32);
        }
        cp_commit();
    }

#pragma unroll
    for (int im = 0; im < 4; im++) {
        int r0 = bm + wm + 16 * im + g;
#pragma unroll
        for (int jn = 0; jn < 8; jn++) {
            int c0 = bn + wn + 8 * jn + 2 * tg;
            float bx = bias[c0], by = bias[c0 + 1];
            float v0 = acc[im][jn][0] + bx, v1 = acc[im][jn][1] + by;
            float v2 = acc[im][jn][2] + bx, v3 = acc[im][jn][3] + by;
            if (HALF_OUT) {
                __half* C = (__half*)Cout;
                *(uint32_t*)(C + (size_t)r0 * N + c0) = packh2(v0, v1);
                *(uint32_t*)(C + (size_t)(r0 + 8) * N + c0) = packh2(v2, v3);
            } else {
                float* C = (float*)Cout;
                *(float2*)(C + (size_t)r0 * N + c0) = make_float2(v0, v1);
                *(float2*)(C + (size_t)(r0 + 8) * N + c0) = make_float2(v2, v3);
            }
        }
    }
}

// ---------------------------------------------------------------------------
// LayerNorm over each 64-wide head segment of q and k, in place, fp16 I/O.
// ---------------------------------------------------------------------------
__global__ __launch_bounds__(256) void qk_ln_h(
    __half* __restrict__ qkv, const float* __restrict__ gamma,
    const float* __restrict__ beta)
{
    int gw = (blockIdx.x * 256 + threadIdx.x) >> 5;
    int lane = threadIdx.x & 31;
    int h = gw % NHEAD;
    int tmp = gw / NHEAD;
    int p = tmp & 1;
    int m = tmp >> 1;
    if (m >= TOKENS) return;

    __half* row = qkv + (size_t)m * QKV_N + p * DIM + h * HD;
    float2 v = __half22float2(*(__half2*)(row + lane * 2));

    float s = v.x + v.y;
#pragma unroll
    for (int o = 16; o; o >>= 1) s += __shfl_xor_sync(0xffffffffu, s, o);
    float mu = s * (1.f / 64.f);
    float dx = v.x - mu, dy = v.y - mu;
    float vs = dx * dx + dy * dy;
#pragma unroll
    for (int o = 16; o; o >>= 1) vs += __shfl_xor_sync(0xffffffffu, vs, o);
    float rstd = rsqrtf(vs * (1.f / 64.f) + 1e-5f);

    float r0 = dx * rstd * gamma[lane * 2 + 0] + beta[lane * 2 + 0];
    float r1 = dy * rstd * gamma[lane * 2 + 1] + beta[lane * 2 + 1];
    *(__half2*)(row + lane * 2) = __floats2half2_rn(r0, r1);
}

// ---------------------------------------------------------------------------
// Flash attention v2: BM=128 (4 warps x 32 rows), BN=64, hd=64.
// K/V double-buffered cp.async. K/V b-fragments reused across 2 m-tiles.
// smem: 2 bufs x (K 8KB + V 8KB); Q staged through buf region first.
// ---------------------------------------------------------------------------
__global__ __launch_bounds__(128, 2) void attn2(
    const __half* __restrict__ qkv, __half* __restrict__ out)
{
    __shared__ __align__(16) unsigned char sm[2 * 16384];

    const int q0 = blockIdx.x * 128;
    const int bh = blockIdx.y;
    const int b = bh / NHEAD, h = bh % NHEAD;
    const int t = threadIdx.x, lane = t & 31, warp = t >> 5;
    const int g = lane >> 2, tg = lane & 3;
    const int ra = (lane & 7) + 8 * ((lane >> 3) & 1), ca = lane >> 4;
    const int rb = (lane & 7) + 8 * (lane >> 4),       cb = (lane >> 3) & 1;
    const uint32_t sbase = smem_u32(sm);
    const float sc = 0.125f * 1.4426950408889634f;

    // ---- Stage Q (128 rows x 64 halves) through first 16KB ----
    {
        const __half* qg = qkv + ((size_t)(b * SEQ + q0)) * QKV_N + h * HD;
#pragma unroll
        for (int l = 0; l < 8; l++) {
            int s = t + l * 128, r = s >> 3, ch = s & 7;
            cp16(sbase + r * 128 + ((ch ^ (r & 7)) * 16),
                 qg + (size_t)r * QKV_N + ch * 8);
        }
        cp_commit();
        cp_wait<0>();
        __syncthreads();
    }
    uint32_t Qa[2][4][4];
#pragma unroll
    for (int mi = 0; mi < 2; mi++) {
        int m = warp * 32 + mi * 16 + ra;
#pragma unroll
        for (int kd = 0; kd < 4; kd++)
            ldsm4(Qa[mi][kd][0], Qa[mi][kd][1], Qa[mi][kd][2], Qa[mi][kd][3],
                  sbase + m * 128 + (((2 * kd + ca) ^ (m & 7)) * 16));
    }
    __syncthreads();

    // ---- K/V pipeline ----
    const __half* kvg = qkv + ((size_t)b * SEQ) * QKV_N + DIM + h * HD;
    // per-thread load slots: l=0..3 -> s=t+l*128: row=s>>3 (0..63), ch=s&7
    int lrow[4], lch[4];
    uint32_t loff[4];
#pragma unroll
    for (int l = 0; l < 4; l++) {
        int s = t + l * 128;
        lrow[l] = s >> 3; lch[l] = s & 7;
        loff[l] = (uint32_t)(lrow[l] * 128 + ((lch[l] ^ (lrow[l] & 7)) * 16));
    }
    // prologue: buf0 <- kv tile 0
    {
#pragma unroll
        for (int l = 0; l < 4; l++) {
            const __half* kg = kvg + (size_t)lrow[l] * QKV_N + lch[l] * 8;
            cp16(sbase + loff[l], kg);
            cp16(sbase + 8192 + loff[l], kg + DIM);
        }
        cp_commit();
    }

    float Oacc[2][8][4];
#pragma unroll
    for (int mi = 0; mi < 2; mi++)
#pragma unroll
        for (int dn = 0; dn < 8; dn++)
#pragma unroll
            for (int c = 0; c < 4; c++) Oacc[mi][dn][c] = 0.f;
    float mM[4] = {-1e30f, -1e30f, -1e30f, -1e30f};
    float lL[4] = {0.f, 0.f, 0.f, 0.f};

    const int NIT = SEQ / 64;   // 16
    for (int it = 0; it < NIT; it++) {
        __syncthreads();   // all warps done with compute(it-1) -> safe to refill
        if (it + 1 < NIT) {
            uint32_t bb = sbase + ((it + 1) & 1) * 16384;
            const __half* kg0 = kvg + (size_t)(it + 1) * 64 * QKV_N;
#pragma unroll
            for (int l = 0; l < 4; l++) {
                const __half* kg = kg0 + (size_t)lrow[l] * QKV_N + lch[l] * 8;
                cp16(bb + loff[l], kg);
                cp16(bb + 8192 + loff[l], kg + DIM);
            }
            cp_commit();
            cp_wait<1>();
        } else {
            cp_wait<0>();
        }
        __syncthreads();
        const uint32_t kb = sbase + (it & 1) * 16384;
        const uint32_t vb = kb + 8192;

        // S = Q @ K^T : S[mi][jn][4], jn over 8 n8-tiles (64 kv cols)
        float S[2][8][4];
#pragma unroll
        for (int mi = 0; mi < 2; mi++)
#pragma unroll
            for (int jn = 0; jn < 8; jn++)
#pragma unroll
                for (int c = 0; c < 4; c++) S[mi][jn][c] = 0.f;
#pragma unroll
        for (int kd = 0; kd < 4; kd++) {
#pragma unroll
            for (int u = 0; u < 4; u++) {
                int n = 16 * u + rb;
                uint32_t b0a, b1a, b0b, b1b;
                ldsm4(b0a, b1a, b0b, b1b,
                      kb + n * 128 + (((2 * kd + cb) ^ (n & 7)) * 16));
#pragma unroll
                for (int mi = 0; mi < 2; mi++) {
                    mma16816(S[mi][2 * u],     Qa[mi][kd][0], Qa[mi][kd][1],
                             Qa[mi][kd][2], Qa[mi][kd][3], b0a, b1a);
                    mma16816(S[mi][2 * u + 1], Qa[mi][kd][0], Qa[mi][kd][1],
                             Qa[mi][kd][2], Qa[mi][kd][3], b0b, b1b);
                }
            }
        }

        // Online softmax per m-tile
        uint32_t Pa[2][4][4];
#pragma unroll
        for (int mi = 0; mi < 2; mi++) {
            float mx0 = -1e30f, mx1 = -1e30f;
#pragma unroll
            for (int jn = 0; jn < 8; jn++) {
                S[mi][jn][0] *= sc; S[mi][jn][1] *= sc;
                S[mi][jn][2] *= sc; S[mi][jn][3] *= sc;
                mx0 = fmaxf(mx0, fmaxf(S[mi][jn][0], S[mi][jn][1]));
                mx1 = fmaxf(mx1, fmaxf(S[mi][jn][2], S[mi][jn][3]));
            }
            mx0 = fmaxf(mx0, __shfl_xor_sync(0xffffffffu, mx0, 1));
            mx0 = fmaxf(mx0, __shfl_xor_sync(0xffffffffu, mx0, 2));
            mx1 = fmaxf(mx1, __shfl_xor_sync(0xffffffffu, mx1, 1));
            mx1 = fmaxf(mx1, __shfl_xor_sync(0xffffffffu, mx1, 2));
            float mn0 = fmaxf(mM[2 * mi], mx0), mn1 = fmaxf(mM[2 * mi + 1], mx1);
            float al0 = ex2f(mM[2 * mi] - mn0), al1 = ex2f(mM[2 * mi + 1] - mn1);
            float s0 = 0.f, s1 = 0.f;
#pragma unroll
            for (int jn = 0; jn < 8; jn++) {
                S[mi][jn][0] = ex2f(S[mi][jn][0] - mn0); s0 += S[mi][jn][0];
                S[mi][jn][1] = ex2f(S[mi][jn][1] - mn0); s0 += S[mi][jn][1];
                S[mi][jn][2] = ex2f(S[mi][jn][2] - mn1); s1 += S[mi][jn][2];
                S[mi][jn][3] = ex2f(S[mi][jn][3] - mn1); s1 += S[mi][jn][3];
            }
            s0 += __shfl_xor_sync(0xffffffffu, s0, 1);
            s0 += __shfl_xor_sync(0xffffffffu, s0, 2);
            s1 += __shfl_xor_sync(0xffffffffu, s1, 1);
            s1 += __shfl_xor_sync(0xffffffffu, s1, 2);
            lL[2 * mi]     = lL[2 * mi] * al0 + s0;     mM[2 * mi] = mn0;
            lL[2 * mi + 1] = lL[2 * mi + 1] * al1 + s1; mM[2 * mi + 1] = mn1;
#pragma unroll
            for (int dn = 0; dn < 8; dn++) {
                Oacc[mi][dn][0] *= al0; Oacc[mi][dn][1] *= al0;
                Oacc[mi][dn][2] *= al1; Oacc[mi][dn][3] *= al1;
            }
#pragma unroll
            for (int kt = 0; kt < 4; kt++) {
                Pa[mi][kt][0] = packh2(S[mi][2 * kt][0],     S[mi][2 * kt][1]);
                Pa[mi][kt][1] = packh2(S[mi][2 * kt][2],     S[mi][2 * kt][3]);
                Pa[mi][kt][2] = packh2(S[mi][2 * kt + 1][0], S[mi][2 * kt + 1][1]);
                Pa[mi][kt][3] = packh2(S[mi][2 * kt + 1][2], S[mi][2 * kt + 1][3]);
            }
        }

        // O += P @ V   (V fragments shared across both m-tiles)
#pragma unroll
        for (int kt = 0; kt < 4; kt++) {
            int j = 16 * kt + ra;
#pragma unroll
            for (int dp = 0; dp < 4; dp++) {
                uint32_t b0a, b1a, b0b, b1b;
                ldsm4t(b0a, b1a, b0b, b1b,
                       vb + j * 128 + (((2 * dp + ca) ^ (j & 7)) * 16));
#pragma unroll
                for (int mi = 0; mi < 2; mi++) {
                    mma16816(Oacc[mi][2 * dp],     Pa[mi][kt][0], Pa[mi][kt][1],
                             Pa[mi][kt][2], Pa[mi][kt][3], b0a, b1a);
                    mma16816(Oacc[mi][2 * dp + 1], Pa[mi][kt][0], Pa[mi][kt][1],
                             Pa[mi][kt][2], Pa[mi][kt][3], b0b, b1b);
                }
            }
        }
    }

    // Epilogue: fp16 out
#pragma unroll
    for (int mi = 0; mi < 2; mi++) {
        float inv0 = 1.f / lL[2 * mi], inv1 = 1.f / lL[2 * mi + 1];
        int r0 = q0 + warp * 32 + mi * 16 + g;
        __half* o0 = out + ((size_t)b * SEQ + r0) * DIM + h * HD;
        __half* o1 = o0 + 8 * DIM;
#pragma unroll
        for (int dn = 0; dn < 8; dn++) {
            int c0 = 8 * dn + 2 * tg;
            *(uint32_t*)(o0 + c0) = packh2(Oacc[mi][dn][0] * inv0,
                                           Oacc[mi][dn][1] * inv0);
            *(uint32_t*)(o1 + c0) = packh2(Oacc[mi][dn][2] * inv1,
                                           Oacc[mi][dn][3] * inv1);
        }
    }
}

// ---------------------------------------------------------------------------
extern "C" void kernel_launch(void* const* d_in, const int* in_sizes, int n_in,
                              void* d_out, int out_size)
{
    const float* x      = (const float*)d_in[0];
    const float* qkv_w  = (const float*)d_in[1];
    const float* qkv_b  = (const float*)d_in[2];
    const float* proj_w = (const float*)d_in[3];
    const float* proj_b = (const float*)d_in[4];
    const float* qn_g   = (const float*)d_in[5];
    const float* qn_b   = (const float*)d_in[6];
    float* out = (float*)d_out;

    __half *xH, *wqH, *wpH, *qkvH, *attnH;
    cudaGetSymbolAddress((void**)&xH,    g_xH);
    cudaGetSymbolAddress((void**)&wqH,   g_wqH);
    cudaGetSymbolAddress((void**)&wpH,   g_wpH);
    cudaGetSymbolAddress((void**)&qkvH,  g_qkvH);
    cudaGetSymbolAddress((void**)&attnH, g_attnH);

    // 0) fp32 -> fp16 conversions
    cvt_f2h<<<TOKENS * DIM / 2048, 256>>>(x, xH, TOKENS * DIM);
    cvt_f2h<<<QKV_N * DIM / 2048, 256>>>(qkv_w, wqH, QKV_N * DIM);
    cvt_f2h<<<DIM * DIM / 2048, 256>>>(proj_w, wpH, DIM * DIM);

    // 1) QKV projection (fp16 out)
    hgemm2<true><<<dim3(QKV_N / 128, TOKENS / 128), 128>>>(
        xH, wqH, qkv_b, qkvH, TOKENS, QKV_N, DIM);

    // 2) LayerNorm q,k in place
    qk_ln_h<<<TOKENS * 2 * NHEAD * 32 / 256, 256>>>(qkvH, qn_g, qn_b);

    // 3) Attention (fp16 out)
    attn2<<<dim3(SEQ / 128, BATCH * NHEAD), 128>>>(qkvH, attnH);

    // 4) Output projection (fp32 out)
    hgemm2<false><<<dim3(DIM / 128, TOKENS / 128), 128>>>(
        attnH, wpH, proj_b, out, TOKENS, DIM, DIM);
}

// round 7
// speedup vs baseline: 3.4446x; 1.1540x over previous
#include <cuda_runtime.h>
#include <cuda_fp16.h>
#include <stdint.h>

#define DIM 768
#define NHEAD 12
#define HD 64
#define BATCH 8
#define SEQ 1024
#define TOKENS (BATCH*SEQ)   // 8192
#define QKV_N (3*DIM)        // 2304

// log2e * headdim^-0.5 folded into q at QKV epilogue
#define QS   (0.125f * 1.4426950408889634f)
// fixed softmax max bound: |S| <= 8*8*0.125*log2e = 11.54 < 12
#define MFIX 12.0f

// Scratch (no allocation allowed)
__device__ __half g_xH  [TOKENS * DIM];
__device__ __half g_wqH [QKV_N * DIM];
__device__ __half g_wpH [DIM * DIM];
__device__ __half g_qkvH[TOKENS * QKV_N];
__device__ __half g_attnH[TOKENS * DIM];

__device__ __forceinline__ float ex2f(float x) {
    float r; asm("ex2.approx.f32 %0, %1;\n" : "=f"(r) : "f"(x)); return r;
}
__device__ __forceinline__ uint32_t smem_u32(const void* p) {
    return (uint32_t)__cvta_generic_to_shared(p);
}
__device__ __forceinline__ uint32_t packh2(float x, float y) {
    __half2 h = __floats2half2_rn(x, y);
    return *reinterpret_cast<uint32_t*>(&h);
}
__device__ __forceinline__ void ldsm4(uint32_t& r0, uint32_t& r1, uint32_t& r2,
                                      uint32_t& r3, uint32_t a) {
    asm volatile("ldmatrix.sync.aligned.m8n8.x4.shared.b16 {%0,%1,%2,%3},[%4];"
                 : "=r"(r0), "=r"(r1), "=r"(r2), "=r"(r3) : "r"(a));
}
__device__ __forceinline__ void ldsm4t(uint32_t& r0, uint32_t& r1, uint32_t& r2,
                                       uint32_t& r3, uint32_t a) {
    asm volatile("ldmatrix.sync.aligned.m8n8.x4.trans.shared.b16 {%0,%1,%2,%3},[%4];"
                 : "=r"(r0), "=r"(r1), "=r"(r2), "=r"(r3) : "r"(a));
}
__device__ __forceinline__ void mma16816(float c[4],
    uint32_t a0, uint32_t a1, uint32_t a2, uint32_t a3, uint32_t b0, uint32_t b1)
{
    asm volatile(
        "mma.sync.aligned.m16n8k16.row.col.f32.f16.f16.f32 "
        "{%0,%1,%2,%3},{%4,%5,%6,%7},{%8,%9},{%0,%1,%2,%3};"
        : "+f"(c[0]), "+f"(c[1]), "+f"(c[2]), "+f"(c[3])
        : "r"(a0), "r"(a1), "r"(a2), "r"(a3), "r"(b0), "r"(b1));
}
__device__ __forceinline__ void cp16(uint32_t dst, const void* src) {
    asm volatile("cp.async.cg.shared.global [%0], [%1], 16;\n" :: "r"(dst), "l"(src));
}
__device__ __forceinline__ void cp_commit() {
    asm volatile("cp.async.commit_group;\n" ::: "memory");
}
template<int N> __device__ __forceinline__ void cp_wait() {
    asm volatile("cp.async.wait_group %0;\n" :: "n"(N) : "memory");
}

// ---------------------------------------------------------------------------
// fp32 -> fp16 conversion
// ---------------------------------------------------------------------------
__global__ __launch_bounds__(256) void cvt_f2h(
    const float* __restrict__ in, __half* __restrict__ out, int n)
{
    int i = blockIdx.x * 256 + threadIdx.x;
    if (i * 8 >= n) return;
    float4 a = ((const float4*)in)[2 * i];
    float4 b = ((const float4*)in)[2 * i + 1];
    uint4 o;
    o.x = packh2(a.x, a.y); o.y = packh2(a.z, a.w);
    o.z = packh2(b.x, b.y); o.w = packh2(b.z, b.w);
    ((uint4*)out)[i] = o;
}

// ---------------------------------------------------------------------------
// fp16 GEMM, mma.m16n8k16: C[m][n] = sum_k A[m][k]*W[n][k] + bias[n]
// 128x128 block, 4 warps (2x2 of 64x64 warp tiles), BK=32, 3-stage cp.async.
// LNQK: fuse per-head(64) LayerNorm into epilogue for n<1536 (q,k regions);
//       q region additionally scaled by QS. Output fp16.
// ---------------------------------------------------------------------------
#define GSTAGES 3
template<bool HALF_OUT, bool LNQK>
__global__ __launch_bounds__(128, 2) void hgemm2(
    const __half* __restrict__ A, const __half* __restrict__ W,
    const float* __restrict__ bias, void* __restrict__ Cout,
    const float* __restrict__ gamma, const float* __restrict__ beta,
    int M, int N, int K)
{
    __shared__ __align__(16) unsigned char sm[GSTAGES * 16384];

    const int bm = blockIdx.y * 128, bn = blockIdx.x * 128;
    const int t = threadIdx.x, lane = t & 31, warp = t >> 5;
    const int wm = (warp & 1) * 64, wn = (warp >> 1) * 64;
    const int g = lane >> 2, tg = lane & 3;
    const int ra = (lane & 7) + 8 * ((lane >> 3) & 1), ca = lane >> 4;
    const int rb = (lane & 7) + 8 * (lane >> 4),       cb = (lane >> 3) & 1;
    const uint32_t sbase = smem_u32(sm);

    uint32_t swo[4];
    const __half* ag[4];
    const __half* wg[4];
#pragma unroll
    for (int l = 0; l < 4; l++) {
        int s = t + l * 128, r = s >> 2, c = s & 3;
        swo[l] = (uint32_t)(r * 64 + ((c ^ ((r >> 1) & 3)) * 16));
        ag[l] = A + (size_t)(bm + r) * K + c * 8;
        wg[l] = W + (size_t)(bn + r) * K + c * 8;
    }

    const int nchunk = K >> 5;
#pragma unroll
    for (int c = 0; c < 2; c++) {
        uint32_t ab = sbase + c * 16384;
#pragma unroll
        for (int l = 0; l < 4; l++) cp16(ab + swo[l], ag[l] + c * 32);
#pragma unroll
        for (int l = 0; l < 4; l++) cp16(ab + 8192 + swo[l], wg[l] + c * 32);
        cp_commit();
    }

    float acc[4][8][4];
#pragma unroll
    for (int i = 0; i < 4; i++)
#pragma unroll
        for (int j = 0; j < 8; j++)
#pragma unroll
            for (int c = 0; c < 4; c++) acc[i][j][c] = 0.f;

    for (int c = 0; c < nchunk; c++) {
        cp_wait<1>();
        __syncthreads();
        const uint32_t ab = sbase + (c % GSTAGES) * 16384;
#pragma unroll
        for (int h = 0; h < 2; h++) {
            uint32_t a[4][4], bf[8][2];
#pragma unroll
            for (int im = 0; im < 4; im++) {
                int m = wm + 16 * im + ra;
                ldsm4(a[im][0], a[im][1], a[im][2], a[im][3],
                      ab + m * 64 + (((2 * h + ca) ^ ((m >> 1) & 3)) * 16));
            }
#pragma unroll
            for (int u = 0; u < 4; u++) {
                int n = wn + 16 * u + rb;
                ldsm4(bf[2 * u][0], bf[2 * u][1], bf[2 * u + 1][0], bf[2 * u + 1][1],
                      ab + 8192 + n * 64 + (((2 * h + cb) ^ ((n >> 1) & 3)) * 16));
            }
#pragma unroll
            for (int im = 0; im < 4; im++)
#pragma unroll
                for (int jn = 0; jn < 8; jn++)
                    mma16816(acc[im][jn], a[im][0], a[im][1], a[im][2], a[im][3],
                             bf[jn][0], bf[jn][1]);
        }
        int pf = c + 2;
        if (pf < nchunk) {
            uint32_t ab2 = sbase + (pf % GSTAGES) * 16384;
#pragma unroll
            for (int l = 0; l < 4; l++) cp16(ab2 + swo[l], ag[l] + pf * 32);
#pragma unroll
            for (int l = 0; l < 4; l++) cp16(ab2 + 8192 + swo[l], wg[l] + pf * 32);
        }
        cp_commit();
    }

    const bool do_ln = LNQK && (bn + wn) < 2 * DIM;   // q or k region
    const float fin = (LNQK && (bn + wn) < DIM) ? QS : 1.f;

#pragma unroll
    for (int im = 0; im < 4; im++) {
        int r0 = bm + wm + 16 * im + g;
        // bias add (all paths)
#pragma unroll
        for (int jn = 0; jn < 8; jn++) {
            int c0 = bn + wn + 8 * jn + 2 * tg;
            float bx = bias[c0], by = bias[c0 + 1];
            acc[im][jn][0] += bx; acc[im][jn][1] += by;
            acc[im][jn][2] += bx; acc[im][jn][3] += by;
        }
        if (do_ln) {
            float s0 = 0.f, ss0 = 0.f, s1 = 0.f, ss1 = 0.f;
#pragma unroll
            for (int jn = 0; jn < 8; jn++) {
                float v0 = acc[im][jn][0], v1 = acc[im][jn][1];
                float v2 = acc[im][jn][2], v3 = acc[im][jn][3];
                s0 += v0 + v1; ss0 += v0 * v0 + v1 * v1;
                s1 += v2 + v3; ss1 += v2 * v2 + v3 * v3;
            }
            s0  += __shfl_xor_sync(0xffffffffu, s0, 1);
            s0  += __shfl_xor_sync(0xffffffffu, s0, 2);
            ss0 += __shfl_xor_sync(0xffffffffu, ss0, 1);
            ss0 += __shfl_xor_sync(0xffffffffu, ss0, 2);
            s1  += __shfl_xor_sync(0xffffffffu, s1, 1);
            s1  += __shfl_xor_sync(0xffffffffu, s1, 2);
            ss1 += __shfl_xor_sync(0xffffffffu, ss1, 1);
            ss1 += __shfl_xor_sync(0xffffffffu, ss1, 2);
            float mu0 = s0 * (1.f / 64.f);
            float mu1 = s1 * (1.f / 64.f);
            float rs0 = rsqrtf(ss0 * (1.f / 64.f) - mu0 * mu0 + 1e-5f);
            float rs1 = rsqrtf(ss1 * (1.f / 64.f) - mu1 * mu1 + 1e-5f);
#pragma unroll
            for (int jn = 0; jn < 8; jn++) {
                int cs = 8 * jn + 2 * tg;
                float ga = gamma[cs], gb = gamma[cs + 1];
                float ba = beta[cs],  bb = beta[cs + 1];
                acc[im][jn][0] = ((acc[im][jn][0] - mu0) * rs0 * ga + ba) * fin;
                acc[im][jn][1] = ((acc[im][jn][1] - mu0) * rs0 * gb + bb) * fin;
                acc[im][jn][2] = ((acc[im][jn][2] - mu1) * rs1 * ga + ba) * fin;
                acc[im][jn][3] = ((acc[im][jn][3] - mu1) * rs1 * gb + bb) * fin;
            }
        }
#pragma unroll
        for (int jn = 0; jn < 8; jn++) {
            int c0 = bn + wn + 8 * jn + 2 * tg;
            if (HALF_OUT) {
                __half* C = (__half*)Cout;
                *(uint32_t*)(C + (size_t)r0 * N + c0) =
                    packh2(acc[im][jn][0], acc[im][jn][1]);
                *(uint32_t*)(C + (size_t)(r0 + 8) * N + c0) =
                    packh2(acc[im][jn][2], acc[im][jn][3]);
            } else {
                float* C = (float*)Cout;
                *(float2*)(C + (size_t)r0 * N + c0) =
                    make_float2(acc[im][jn][0], acc[im][jn][1]);
                *(float2*)(C + (size_t)(r0 + 8) * N + c0) =
                    make_float2(acc[im][jn][2], acc[im][jn][3]);
            }
        }
    }
}

// ---------------------------------------------------------------------------
// Flash attention, fixed-max softmax (scores bounded: LN'd q,k).
// BM=128 (4 warps x 32 rows), BN=64, hd=64. K/V double-buffered cp.async.
// q pre-scaled by QS at QKV epilogue -> P = ex2(S - MFIX). No online max,
// no Oacc rescale; row sums deferred to epilogue.
// ---------------------------------------------------------------------------
__global__ __launch_bounds__(128, 2) void attn2(
    const __half* __restrict__ qkv, __half* __restrict__ out)
{
    __shared__ __align__(16) unsigned char sm[2 * 16384];

    const int q0 = blockIdx.x * 128;
    const int bh = blockIdx.y;
    const int b = bh / NHEAD, h = bh % NHEAD;
    const int t = threadIdx.x, lane = t & 31, warp = t >> 5;
    const int g = lane >> 2, tg = lane & 3;
    const int ra = (lane & 7) + 8 * ((lane >> 3) & 1), ca = lane >> 4;
    const int rb = (lane & 7) + 8 * (lane >> 4),       cb = (lane >> 3) & 1;
    const uint32_t sbase = smem_u32(sm);

    // ---- Stage Q (128 rows x 64 halves) ----
    {
        const __half* qg = qkv + ((size_t)(b * SEQ + q0)) * QKV_N + h * HD;
#pragma unroll
        for (int l = 0; l < 8; l++) {
            int s = t + l * 128, r = s >> 3, ch = s & 7;
            cp16(sbase + r * 128 + ((ch ^ (r & 7)) * 16),
                 qg + (size_t)r * QKV_N + ch * 8);
        }
        cp_commit();
        cp_wait<0>();
        __syncthreads();
    }
    uint32_t Qa[2][4][4];
#pragma unroll
    for (int mi = 0; mi < 2; mi++) {
        int m = warp * 32 + mi * 16 + ra;
#pragma unroll
        for (int kd = 0; kd < 4; kd++)
            ldsm4(Qa[mi][kd][0], Qa[mi][kd][1], Qa[mi][kd][2], Qa[mi][kd][3],
                  sbase + m * 128 + (((2 * kd + ca) ^ (m & 7)) * 16));
    }
    __syncthreads();

    const __half* kvg = qkv + ((size_t)b * SEQ) * QKV_N + DIM + h * HD;
    int lrow[4], lch[4];
    uint32_t loff[4];
#pragma unroll
    for (int l = 0; l < 4; l++) {
        int s = t + l * 128;
        lrow[l] = s >> 3; lch[l] = s & 7;
        loff[l] = (uint32_t)(lrow[l] * 128 + ((lch[l] ^ (lrow[l] & 7)) * 16));
    }
    {
#pragma unroll
        for (int l = 0; l < 4; l++) {
            const __half* kg = kvg + (size_t)lrow[l] * QKV_N + lch[l] * 8;
            cp16(sbase + loff[l], kg);
            cp16(sbase + 8192 + loff[l], kg + DIM);
        }
        cp_commit();
    }

    float Oacc[2][8][4];
#pragma unroll
    for (int mi = 0; mi < 2; mi++)
#pragma unroll
        for (int dn = 0; dn < 8; dn++)
#pragma unroll
            for (int c = 0; c < 4; c++) Oacc[mi][dn][c] = 0.f;
    float lL[4] = {0.f, 0.f, 0.f, 0.f};

    const int NIT = SEQ / 64;   // 16
    for (int it = 0; it < NIT; it++) {
        __syncthreads();
        if (it + 1 < NIT) {
            uint32_t bb = sbase + ((it + 1) & 1) * 16384;
            const __half* kg0 = kvg + (size_t)(it + 1) * 64 * QKV_N;
#pragma unroll
            for (int l = 0; l < 4; l++) {
                const __half* kg = kg0 + (size_t)lrow[l] * QKV_N + lch[l] * 8;
                cp16(bb + loff[l], kg);
                cp16(bb + 8192 + loff[l], kg + DIM);
            }
            cp_commit();
            cp_wait<1>();
        } else {
            cp_wait<0>();
        }
        __syncthreads();
        const uint32_t kb = sbase + (it & 1) * 16384;
        const uint32_t vb = kb + 8192;

        // S = Q @ K^T   (S already in log2 units, scale folded into q)
        float S[2][8][4];
#pragma unroll
        for (int mi = 0; mi < 2; mi++)
#pragma unroll
            for (int jn = 0; jn < 8; jn++)
#pragma unroll
                for (int c = 0; c < 4; c++) S[mi][jn][c] = 0.f;
#pragma unroll
        for (int kd = 0; kd < 4; kd++) {
#pragma unroll
            for (int u = 0; u < 4; u++) {
                int n = 16 * u + rb;
                uint32_t b0a, b1a, b0b, b1b;
                ldsm4(b0a, b1a, b0b, b1b,
                      kb + n * 128 + (((2 * kd + cb) ^ (n & 7)) * 16));
#pragma unroll
                for (int mi = 0; mi < 2; mi++) {
                    mma16816(S[mi][2 * u],     Qa[mi][kd][0], Qa[mi][kd][1],
                             Qa[mi][kd][2], Qa[mi][kd][3], b0a, b1a);
                    mma16816(S[mi][2 * u + 1], Qa[mi][kd][0], Qa[mi][kd][1],
                             Qa[mi][kd][2], Qa[mi][kd][3], b0b, b1b);
                }
            }
        }

        // Fixed-max softmax: P = ex2(S - MFIX); accumulate per-lane partial sums
        uint32_t Pa[2][4][4];
#pragma unroll
        for (int mi = 0; mi < 2; mi++) {
            float p[8][4];
#pragma unroll
            for (int jn = 0; jn < 8; jn++) {
                p[jn][0] = ex2f(S[mi][jn][0] - MFIX);
                p[jn][1] = ex2f(S[mi][jn][1] - MFIX);
                p[jn][2] = ex2f(S[mi][jn][2] - MFIX);
                p[jn][3] = ex2f(S[mi][jn][3] - MFIX);
                lL[2 * mi]     += p[jn][0] + p[jn][1];
                lL[2 * mi + 1] += p[jn][2] + p[jn][3];
            }
#pragma unroll
            for (int kt = 0; kt < 4; kt++) {
                Pa[mi][kt][0] = packh2(p[2 * kt][0],     p[2 * kt][1]);
                Pa[mi][kt][1] = packh2(p[2 * kt][2],     p[2 * kt][3]);
                Pa[mi][kt][2] = packh2(p[2 * kt + 1][0], p[2 * kt + 1][1]);
                Pa[mi][kt][3] = packh2(p[2 * kt + 1][2], p[2 * kt + 1][3]);
            }
        }

        // O += P @ V
#pragma unroll
        for (int kt = 0; kt < 4; kt++) {
            int j = 16 * kt + ra;
#pragma unroll
            for (int dp = 0; dp < 4; dp++) {
                uint32_t b0a, b1a, b0b, b1b;
                ldsm4t(b0a, b1a, b0b, b1b,
                       vb + j * 128 + (((2 * dp + ca) ^ (j & 7)) * 16));
#pragma unroll
                for (int mi = 0; mi < 2; mi++) {
                    mma16816(Oacc[mi][2 * dp],     Pa[mi][kt][0], Pa[mi][kt][1],
                             Pa[mi][kt][2], Pa[mi][kt][3], b0a, b1a);
                    mma16816(Oacc[mi][2 * dp + 1], Pa[mi][kt][0], Pa[mi][kt][1],
                             Pa[mi][kt][2], Pa[mi][kt][3], b0b, b1b);
                }
            }
        }
    }

    // Complete row sums across the lane quad, then normalize + store
#pragma unroll
    for (int r = 0; r < 4; r++) {
        lL[r] += __shfl_xor_sync(0xffffffffu, lL[r], 1);
        lL[r] += __shfl_xor_sync(0xffffffffu, lL[r], 2);
    }
#pragma unroll
    for (int mi = 0; mi < 2; mi++) {
        float inv0 = 1.f / lL[2 * mi], inv1 = 1.f / lL[2 * mi + 1];
        int r0 = q0 + warp * 32 + mi * 16 + g;
        __half* o0 = out + ((size_t)b * SEQ + r0) * DIM + h * HD;
        __half* o1 = o0 + 8 * DIM;
#pragma unroll
        for (int dn = 0; dn < 8; dn++) {
            int c0 = 8 * dn + 2 * tg;
            *(uint32_t*)(o0 + c0) = packh2(Oacc[mi][dn][0] * inv0,
                                           Oacc[mi][dn][1] * inv0);
            *(uint32_t*)(o1 + c0) = packh2(Oacc[mi][dn][2] * inv1,
                                           Oacc[mi][dn][3] * inv1);
        }
    }
}

// ---------------------------------------------------------------------------
extern "C" void kernel_launch(void* const* d_in, const int* in_sizes, int n_in,
                              void* d_out, int out_size)
{
    const float* x      = (const float*)d_in[0];
    const float* qkv_w  = (const float*)d_in[1];
    const float* qkv_b  = (const float*)d_in[2];
    const float* proj_w = (const float*)d_in[3];
    const float* proj_b = (const float*)d_in[4];
    const float* qn_g   = (const float*)d_in[5];
    const float* qn_b   = (const float*)d_in[6];
    float* out = (float*)d_out;

    __half *xH, *wqH, *wpH, *qkvH, *attnH;
    cudaGetSymbolAddress((void**)&xH,    g_xH);
    cudaGetSymbolAddress((void**)&wqH,   g_wqH);
    cudaGetSymbolAddress((void**)&wpH,   g_wpH);
    cudaGetSymbolAddress((void**)&qkvH,  g_qkvH);
    cudaGetSymbolAddress((void**)&attnH, g_attnH);

    // 0) fp32 -> fp16 conversions
    cvt_f2h<<<TOKENS * DIM / 2048, 256>>>(x, xH, TOKENS * DIM);
    cvt_f2h<<<QKV_N * DIM / 2048, 256>>>(qkv_w, wqH, QKV_N * DIM);
    cvt_f2h<<<DIM * DIM / 2048, 256>>>(proj_w, wpH, DIM * DIM);

    // 1) QKV projection + fused LayerNorm(q,k) + q-scale (fp16 out)
    hgemm2<true, true><<<dim3(QKV_N / 128, TOKENS / 128), 128>>>(
        xH, wqH, qkv_b, qkvH, qn_g, qn_b, TOKENS, QKV_N, DIM);

    // 2) Attention, fixed-max softmax (fp16 out)
    attn2<<<dim3(SEQ / 128, BATCH * NHEAD), 128>>>(qkvH, attnH);

    // 3) Output projection (fp32 out)
    hgemm2<false, false><<<dim3(DIM / 128, TOKENS / 128), 128>>>(
        attnH, wpH, proj_b, out, nullptr, nullptr, TOKENS, DIM, DIM);
}

// round 8
// speedup vs baseline: 3.6174x; 1.0502x over previous
#include <cuda_runtime.h>
#include <cuda_fp16.h>
#include <stdint.h>

#define DIM 768
#define NHEAD 12
#define HD 64
#define BATCH 8
#define SEQ 1024
#define TOKENS (BATCH*SEQ)   // 8192
#define QKV_N (3*DIM)        // 2304

// log2e * headdim^-0.5 folded into q at QKV epilogue -> S is in log2 units.
#define QS   (0.125f * 1.4426950408889634f)
#define ONESH2 0x3C003C00u   // half2(1.0, 1.0)

// Scratch (no allocation allowed)
__device__ __half g_xH  [TOKENS * DIM];
__device__ __half g_wqH [QKV_N * DIM];
__device__ __half g_wpH [DIM * DIM];
__device__ __half g_qkvH[TOKENS * QKV_N];
__device__ __half g_attnH[TOKENS * DIM];

__device__ __forceinline__ uint32_t smem_u32(const void* p) {
    return (uint32_t)__cvta_generic_to_shared(p);
}
__device__ __forceinline__ uint32_t packh2(float x, float y) {
    __half2 h = __floats2half2_rn(x, y);
    return *reinterpret_cast<uint32_t*>(&h);
}
__device__ __forceinline__ uint32_t ex2x2(uint32_t x) {
    uint32_t r;
    asm("ex2.approx.f16x2 %0, %1;\n" : "=r"(r) : "r"(x));
    return r;
}
__device__ __forceinline__ void ldsm4(uint32_t& r0, uint32_t& r1, uint32_t& r2,
                                      uint32_t& r3, uint32_t a) {
    asm volatile("ldmatrix.sync.aligned.m8n8.x4.shared.b16 {%0,%1,%2,%3},[%4];"
                 : "=r"(r0), "=r"(r1), "=r"(r2), "=r"(r3) : "r"(a));
}
__device__ __forceinline__ void ldsm4t(uint32_t& r0, uint32_t& r1, uint32_t& r2,
                                       uint32_t& r3, uint32_t a) {
    asm volatile("ldmatrix.sync.aligned.m8n8.x4.trans.shared.b16 {%0,%1,%2,%3},[%4];"
                 : "=r"(r0), "=r"(r1), "=r"(r2), "=r"(r3) : "r"(a));
}
__device__ __forceinline__ void mma16816(float c[4],
    uint32_t a0, uint32_t a1, uint32_t a2, uint32_t a3, uint32_t b0, uint32_t b1)
{
    asm volatile(
        "mma.sync.aligned.m16n8k16.row.col.f32.f16.f16.f32 "
        "{%0,%1,%2,%3},{%4,%5,%6,%7},{%8,%9},{%0,%1,%2,%3};"
        : "+f"(c[0]), "+f"(c[1]), "+f"(c[2]), "+f"(c[3])
        : "r"(a0), "r"(a1), "r"(a2), "r"(a3), "r"(b0), "r"(b1));
}
__device__ __forceinline__ void cp16(uint32_t dst, const void* src) {
    asm volatile("cp.async.cg.shared.global [%0], [%1], 16;\n" :: "r"(dst), "l"(src));
}
__device__ __forceinline__ void cp_commit() {
    asm volatile("cp.async.commit_group;\n" ::: "memory");
}
template<int N> __device__ __forceinline__ void cp_wait() {
    asm volatile("cp.async.wait_group %0;\n" :: "n"(N) : "memory");
}

// ---------------------------------------------------------------------------
// fused fp32 -> fp16 conversion of x, qkv_w, proj_w in one launch
// ---------------------------------------------------------------------------
#define CV1 (TOKENS * DIM / 8)
#define CV2 (CV1 + QKV_N * DIM / 8)
#define CV3 (CV2 + DIM * DIM / 8)
__global__ __launch_bounds__(256) void cvt_all(
    const float* __restrict__ x, const float* __restrict__ wq,
    const float* __restrict__ wp, __half* __restrict__ xH,
    __half* __restrict__ wqH, __half* __restrict__ wpH)
{
    int i = blockIdx.x * 256 + threadIdx.x;
    const float* in;
    __half* out;
    int j;
    if (i < CV1)      { in = x;  out = xH;  j = i; }
    else if (i < CV2) { in = wq; out = wqH; j = i - CV1; }
    else if (i < CV3) { in = wp; out = wpH; j = i - CV2; }
    else return;
    float4 a = ((const float4*)in)[2 * j];
    float4 b = ((const float4*)in)[2 * j + 1];
    uint4 o;
    o.x = packh2(a.x, a.y); o.y = packh2(a.z, a.w);
    o.z = packh2(b.x, b.y); o.w = packh2(b.z, b.w);
    ((uint4*)out)[j] = o;
}

// ---------------------------------------------------------------------------
// fp16 GEMM, mma.m16n8k16: C[m][n] = sum_k A[m][k]*W[n][k] + bias[n]
// 128x128 block, 4 warps (2x2 of 64x64 warp tiles), BK=32, 3-stage cp.async.
// LNQK: fuse per-head(64) LayerNorm into epilogue for n<1536 (q,k regions);
//       q region additionally scaled by QS. Output fp16.
// ---------------------------------------------------------------------------
#define GSTAGES 3
template<bool HALF_OUT, bool LNQK>
__global__ __launch_bounds__(128, 2) void hgemm2(
    const __half* __restrict__ A, const __half* __restrict__ W,
    const float* __restrict__ bias, void* __restrict__ Cout,
    const float* __restrict__ gamma, const float* __restrict__ beta,
    int M, int N, int K)
{
    __shared__ __align__(16) unsigned char sm[GSTAGES * 16384];

    const int bm = blockIdx.y * 128, bn = blockIdx.x * 128;
    const int t = threadIdx.x, lane = t & 31, warp = t >> 5;
    const int wm = (warp & 1) * 64, wn = (warp >> 1) * 64;
    const int g = lane >> 2, tg = lane & 3;
    const int ra = (lane & 7) + 8 * ((lane >> 3) & 1), ca = lane >> 4;
    const int rb = (lane & 7) + 8 * (lane >> 4),       cb = (lane >> 3) & 1;
    const uint32_t sbase = smem_u32(sm);

    uint32_t swo[4];
    const __half* ag[4];
    const __half* wg[4];
#pragma unroll
    for (int l = 0; l < 4; l++) {
        int s = t + l * 128, r = s >> 2, c = s & 3;
        swo[l] = (uint32_t)(r * 64 + ((c ^ ((r >> 1) & 3)) * 16));
        ag[l] = A + (size_t)(bm + r) * K + c * 8;
        wg[l] = W + (size_t)(bn + r) * K + c * 8;
    }

    const int nchunk = K >> 5;
#pragma unroll
    for (int c = 0; c < 2; c++) {
        uint32_t ab = sbase + c * 16384;
#pragma unroll
        for (int l = 0; l < 4; l++) cp16(ab + swo[l], ag[l] + c * 32);
#pragma unroll
        for (int l = 0; l < 4; l++) cp16(ab + 8192 + swo[l], wg[l] + c * 32);
        cp_commit();
    }

    float acc[4][8][4];
#pragma unroll
    for (int i = 0; i < 4; i++)
#pragma unroll
        for (int j = 0; j < 8; j++)
#pragma unroll
            for (int c = 0; c < 4; c++) acc[i][j][c] = 0.f;

    for (int c = 0; c < nchunk; c++) {
        cp_wait<1>();
        __syncthreads();
        const uint32_t ab = sbase + (c % GSTAGES) * 16384;
#pragma unroll
        for (int h = 0; h < 2; h++) {
            uint32_t a[4][4], bf[8][2];
#pragma unroll
            for (int im = 0; im < 4; im++) {
                int m = wm + 16 * im + ra;
                ldsm4(a[im][0], a[im][1], a[im][2], a[im][3],
                      ab + m * 64 + (((2 * h + ca) ^ ((m >> 1) & 3)) * 16));
            }
#pragma unroll
            for (int u = 0; u < 4; u++) {
                int n = wn + 16 * u + rb;
                ldsm4(bf[2 * u][0], bf[2 * u][1], bf[2 * u + 1][0], bf[2 * u + 1][1],
                      ab + 8192 + n * 64 + (((2 * h + cb) ^ ((n >> 1) & 3)) * 16));
            }
#pragma unroll
            for (int im = 0; im < 4; im++)
#pragma unroll
                for (int jn = 0; jn < 8; jn++)
                    mma16816(acc[im][jn], a[im][0], a[im][1], a[im][2], a[im][3],
                             bf[jn][0], bf[jn][1]);
        }
        int pf = c + 2;
        if (pf < nchunk) {
            uint32_t ab2 = sbase + (pf % GSTAGES) * 16384;
#pragma unroll
            for (int l = 0; l < 4; l++) cp16(ab2 + swo[l], ag[l] + pf * 32);
#pragma unroll
            for (int l = 0; l < 4; l++) cp16(ab2 + 8192 + swo[l], wg[l] + pf * 32);
        }
        cp_commit();
    }

    const bool do_ln = LNQK && (bn + wn) < 2 * DIM;   // q or k region
    const float fin = (LNQK && (bn + wn) < DIM) ? QS : 1.f;

#pragma unroll
    for (int im = 0; im < 4; im++) {
        int r0 = bm + wm + 16 * im + g;
#pragma unroll
        for (int jn = 0; jn < 8; jn++) {
            int c0 = bn + wn + 8 * jn + 2 * tg;
            float bx = bias[c0], by = bias[c0 + 1];
            acc[im][jn][0] += bx; acc[im][jn][1] += by;
            acc[im][jn][2] += bx; acc[im][jn][3] += by;
        }
        if (do_ln) {
            float s0 = 0.f, ss0 = 0.f, s1 = 0.f, ss1 = 0.f;
#pragma unroll
            for (int jn = 0; jn < 8; jn++) {
                float v0 = acc[im][jn][0], v1 = acc[im][jn][1];
                float v2 = acc[im][jn][2], v3 = acc[im][jn][3];
                s0 += v0 + v1; ss0 += v0 * v0 + v1 * v1;
                s1 += v2 + v3; ss1 += v2 * v2 + v3 * v3;
            }
            s0  += __shfl_xor_sync(0xffffffffu, s0, 1);
            s0  += __shfl_xor_sync(0xffffffffu, s0, 2);
            ss0 += __shfl_xor_sync(0xffffffffu, ss0, 1);
            ss0 += __shfl_xor_sync(0xffffffffu, ss0, 2);
            s1  += __shfl_xor_sync(0xffffffffu, s1, 1);
            s1  += __shfl_xor_sync(0xffffffffu, s1, 2);
            ss1 += __shfl_xor_sync(0xffffffffu, ss1, 1);
            ss1 += __shfl_xor_sync(0xffffffffu, ss1, 2);
            float mu0 = s0 * (1.f / 64.f);
            float mu1 = s1 * (1.f / 64.f);
            float rs0 = rsqrtf(ss0 * (1.f / 64.f) - mu0 * mu0 + 1e-5f);
            float rs1 = rsqrtf(ss1 * (1.f / 64.f) - mu1 * mu1 + 1e-5f);
#pragma unroll
            for (int jn = 0; jn < 8; jn++) {
                int cs = 8 * jn + 2 * tg;
                float ga = gamma[cs], gb = gamma[cs + 1];
                float ba = beta[cs],  bb = beta[cs + 1];
                acc[im][jn][0] = ((acc[im][jn][0] - mu0) * rs0 * ga + ba) * fin;
                acc[im][jn][1] = ((acc[im][jn][1] - mu0) * rs0 * gb + bb) * fin;
                acc[im][jn][2] = ((acc[im][jn][2] - mu1) * rs1 * ga + ba) * fin;
                acc[im][jn][3] = ((acc[im][jn][3] - mu1) * rs1 * gb + bb) * fin;
            }
        }
#pragma unroll
        for (int jn = 0; jn < 8; jn++) {
            int c0 = bn + wn + 8 * jn + 2 * tg;
            if (HALF_OUT) {
                __half* C = (__half*)Cout;
                *(uint32_t*)(C + (size_t)r0 * N + c0) =
                    packh2(acc[im][jn][0], acc[im][jn][1]);
                *(uint32_t*)(C + (size_t)(r0 + 8) * N + c0) =
                    packh2(acc[im][jn][2], acc[im][jn][3]);
            } else {
                float* C = (float*)Cout;
                *(float2*)(C + (size_t)r0 * N + c0) =
                    make_float2(acc[im][jn][0], acc[im][jn][1]);
                *(float2*)(C + (size_t)(r0 + 8) * N + c0) =
                    make_float2(acc[im][jn][2], acc[im][jn][3]);
            }
        }
    }
}

// ---------------------------------------------------------------------------
// Flash attention, unnormalized softmax (P = 2^S, normalization cancels the
// missing max-shift; LN'd q,k bound |S|<=11.6 so 2^S fits fp16).
// BM=128 (4 warps x 32 rows), BN=64, hd=64. Triple-buffered K/V cp.async,
// ONE __syncthreads per iteration. Row sums via all-ones MMA (no shuffles).
// ex2 done in fp16x2 (half the MUFU ops).
// ---------------------------------------------------------------------------
__global__ __launch_bounds__(128, 2) void attn3(
    const __half* __restrict__ qkv, __half* __restrict__ out)
{
    __shared__ __align__(16) unsigned char sm[3 * 16384];   // 48KB

    const int q0 = blockIdx.x * 128;
    const int bh = blockIdx.y;
    const int b = bh / NHEAD, h = bh % NHEAD;
    const int t = threadIdx.x, lane = t & 31, warp = t >> 5;
    const int g = lane >> 2, tg = lane & 3;
    const int ra = (lane & 7) + 8 * ((lane >> 3) & 1), ca = lane >> 4;
    const int rb = (lane & 7) + 8 * (lane >> 4),       cb = (lane >> 3) & 1;
    const uint32_t sbase = smem_u32(sm);

    const __half* kvg = qkv + ((size_t)b * SEQ) * QKV_N + DIM + h * HD;
    int lrow[4], lch[4];
    uint32_t loff[4];
#pragma unroll
    for (int l = 0; l < 4; l++) {
        int s = t + l * 128;
        lrow[l] = s >> 3; lch[l] = s & 7;
        loff[l] = (uint32_t)(lrow[l] * 128 + ((lch[l] ^ (lrow[l] & 7)) * 16));
    }

    // ---- Stage Q into buf2; prefetch KV0 into buf0 concurrently ----
    {
        const __half* qg = qkv + ((size_t)(b * SEQ + q0)) * QKV_N + h * HD;
        uint32_t qb = sbase + 2 * 16384;
#pragma unroll
        for (int l = 0; l < 8; l++) {
            int s = t + l * 128, r = s >> 3, ch = s & 7;
            cp16(qb + r * 128 + ((ch ^ (r & 7)) * 16),
                 qg + (size_t)r * QKV_N + ch * 8);
        }
        cp_commit();
#pragma unroll
        for (int l = 0; l < 4; l++) {
            const __half* kg = kvg + (size_t)lrow[l] * QKV_N + lch[l] * 8;
            cp16(sbase + loff[l], kg);
            cp16(sbase + 8192 + loff[l], kg + DIM);
        }
        cp_commit();
        cp_wait<1>();   // Q ready (KV0 may still be in flight)
        __syncthreads();
    }
    uint32_t Qa[2][4][4];
    {
        uint32_t qb = sbase + 2 * 16384;
#pragma unroll
        for (int mi = 0; mi < 2; mi++) {
            int m = warp * 32 + mi * 16 + ra;
#pragma unroll
            for (int kd = 0; kd < 4; kd++)
                ldsm4(Qa[mi][kd][0], Qa[mi][kd][1], Qa[mi][kd][2], Qa[mi][kd][3],
                      qb + m * 128 + (((2 * kd + ca) ^ (m & 7)) * 16));
        }
    }
    __syncthreads();   // buf2 free for KV reuse

    float Oacc[2][8][4];
#pragma unroll
    for (int mi = 0; mi < 2; mi++)
#pragma unroll
        for (int dn = 0; dn < 8; dn++)
#pragma unroll
            for (int c = 0; c < 4; c++) Oacc[mi][dn][c] = 0.f;
    float Lacc[2][4];
#pragma unroll
    for (int mi = 0; mi < 2; mi++)
#pragma unroll
        for (int c = 0; c < 4; c++) Lacc[mi][c] = 0.f;

    const int NIT = SEQ / 64;   // 16
    for (int it = 0; it < NIT; it++) {
        // prefetch KV(it+1) into buf (it+1)%3 (distinct from bufs used by
        // iters it and it-1 -> safe with the single barrier below)
        if (it + 1 < NIT) {
            uint32_t bb = sbase + ((it + 1) % 3) * 16384;
            const __half* kg0 = kvg + (size_t)(it + 1) * 64 * QKV_N;
#pragma unroll
            for (int l = 0; l < 4; l++) {
                const __half* kg = kg0 + (size_t)lrow[l] * QKV_N + lch[l] * 8;
                cp16(bb + loff[l], kg);
                cp16(bb + 8192 + loff[l], kg + DIM);
            }
        }
        cp_commit();
        cp_wait<1>();    // KV(it) complete
        __syncthreads();
        const uint32_t kb = sbase + (it % 3) * 16384;
        const uint32_t vb = kb + 8192;

        // S = Q @ K^T (log2 units; QS folded into q)
        float S[2][8][4];
#pragma unroll
        for (int mi = 0; mi < 2; mi++)
#pragma unroll
            for (int jn = 0; jn < 8; jn++)
#pragma unroll
                for (int c = 0; c < 4; c++) S[mi][jn][c] = 0.f;
#pragma unroll
        for (int kd = 0; kd < 4; kd++) {
#pragma unroll
            for (int u = 0; u < 4; u++) {
                int n = 16 * u + rb;
                uint32_t b0a, b1a, b0b, b1b;
                ldsm4(b0a, b1a, b0b, b1b,
                      kb + n * 128 + (((2 * kd + cb) ^ (n & 7)) * 16));
#pragma unroll
                for (int mi = 0; mi < 2; mi++) {
                    mma16816(S[mi][2 * u],     Qa[mi][kd][0], Qa[mi][kd][1],
                             Qa[mi][kd][2], Qa[mi][kd][3], b0a, b1a);
                    mma16816(S[mi][2 * u + 1], Qa[mi][kd][0], Qa[mi][kd][1],
                             Qa[mi][kd][2], Qa[mi][kd][3], b0b, b1b);
                }
            }
        }

        // P = 2^S in fp16 (pack first, one MUFU per 2 values)
        uint32_t Pa[2][4][4];
#pragma unroll
        for (int mi = 0; mi < 2; mi++) {
#pragma unroll
            for (int kt = 0; kt < 4; kt++) {
                Pa[mi][kt][0] = ex2x2(packh2(S[mi][2 * kt][0],     S[mi][2 * kt][1]));
                Pa[mi][kt][1] = ex2x2(packh2(S[mi][2 * kt][2],     S[mi][2 * kt][3]));
                Pa[mi][kt][2] = ex2x2(packh2(S[mi][2 * kt + 1][0], S[mi][2 * kt + 1][1]));
                Pa[mi][kt][3] = ex2x2(packh2(S[mi][2 * kt + 1][2], S[mi][2 * kt + 1][3]));
            }
            // row sums via all-ones MMA: Lacc[mi][0]=row g, [2]=row g+8
#pragma unroll
            for (int kt = 0; kt < 4; kt++)
                mma16816(Lacc[mi], Pa[mi][kt][0], Pa[mi][kt][1],
                         Pa[mi][kt][2], Pa[mi][kt][3], ONESH2, ONESH2);
        }

        // O += P @ V
#pragma unroll
        for (int kt = 0; kt < 4; kt++) {
            int j = 16 * kt + ra;
#pragma unroll
            for (int dp = 0; dp < 4; dp++) {
                uint32_t b0a, b1a, b0b, b1b;
                ldsm4t(b0a, b1a, b0b, b1b,
                       vb + j * 128 + (((2 * dp + ca) ^ (j & 7)) * 16));
#pragma unroll
                for (int mi = 0; mi < 2; mi++) {
                    mma16816(Oacc[mi][2 * dp],     Pa[mi][kt][0], Pa[mi][kt][1],
                             Pa[mi][kt][2], Pa[mi][kt][3], b0a, b1a);
                    mma16816(Oacc[mi][2 * dp + 1], Pa[mi][kt][0], Pa[mi][kt][1],
                             Pa[mi][kt][2], Pa[mi][kt][3], b0b, b1b);
                }
            }
        }
    }

    // Normalize + store (row sums already complete per-lane)
#pragma unroll
    for (int mi = 0; mi < 2; mi++) {
        float inv0 = 1.f / Lacc[mi][0], inv1 = 1.f / Lacc[mi][2];
        int r0 = q0 + warp * 32 + mi * 16 + g;
        __half* o0 = out + ((size_t)b * SEQ + r0) * DIM + h * HD;
        __half* o1 = o0 + 8 * DIM;
#pragma unroll
        for (int dn = 0; dn < 8; dn++) {
            int c0 = 8 * dn + 2 * tg;
            *(uint32_t*)(o0 + c0) = packh2(Oacc[mi][dn][0] * inv0,
                                           Oacc[mi][dn][1] * inv0);
            *(uint32_t*)(o1 + c0) = packh2(Oacc[mi][dn][2] * inv1,
                                           Oacc[mi][dn][3] * inv1);
        }
    }
}

// ---------------------------------------------------------------------------
extern "C" void kernel_launch(void* const* d_in, const int* in_sizes, int n_in,
                              void* d_out, int out_size)
{
    const float* x      = (const float*)d_in[0];
    const float* qkv_w  = (const float*)d_in[1];
    const float* qkv_b  = (const float*)d_in[2];
    const float* proj_w = (const float*)d_in[3];
    const float* proj_b = (const float*)d_in[4];
    const float* qn_g   = (const float*)d_in[5];
    const float* qn_b   = (const float*)d_in[6];
    float* out = (float*)d_out;

    __half *xH, *wqH, *wpH, *qkvH, *attnH;
    cudaGetSymbolAddress((void**)&xH,    g_xH);
    cudaGetSymbolAddress((void**)&wqH,   g_wqH);
    cudaGetSymbolAddress((void**)&wpH,   g_wpH);
    cudaGetSymbolAddress((void**)&qkvH,  g_qkvH);
    cudaGetSymbolAddress((void**)&attnH, g_attnH);

    // 0) all fp32 -> fp16 conversions in one launch
    cvt_all<<<(CV3 + 255) / 256, 256>>>(x, qkv_w, proj_w, xH, wqH, wpH);

    // 1) QKV projection + fused LayerNorm(q,k) + q-scale (fp16 out)
    hgemm2<true, true><<<dim3(QKV_N / 128, TOKENS / 128), 128>>>(
        xH, wqH, qkv_b, qkvH, qn_g, qn_b, TOKENS, QKV_N, DIM);

    // 2) Attention, unnormalized-exponent softmax (fp16 out)
    attn3<<<dim3(SEQ / 128, BATCH * NHEAD), 128>>>(qkvH, attnH);

    // 3) Output projection (fp32 out)
    hgemm2<false, false><<<dim3(DIM / 128, TOKENS / 128), 128>>>(
        attnH, wpH, proj_b, out, nullptr, nullptr, TOKENS, DIM, DIM);
}